// round 9
// baseline (speedup 1.0000x reference)
#include <cuda_runtime.h>
#include <cuda_bf16.h>
#include <cstdint>
#include <math.h>

#define BB 8
#define TT 512
#define CC 1024
#define HH 16
#define EE 64
#define LL 2048
#define SQ 2560                     // L + T
#define QSCALE 0.1803368801111244f  // 0.125 * log2(e)

// ---------------------------------------------------------------------------
// Scratch (__device__ globals; no allocation allowed)
// ---------------------------------------------------------------------------
__device__ __nv_bfloat16 g_xhi[BB*TT*CC];
__device__ __nv_bfloat16 g_xlo[BB*TT*CC];
__device__ __nv_bfloat16 g_yhi[BB*TT*CC];
__device__ __nv_bfloat16 g_ylo[BB*TT*CC];
__device__ __nv_bfloat16 g_wqkv_hi[3*CC*CC];   // [N=3072][K=1024]
__device__ __nv_bfloat16 g_wqkv_lo[3*CC*CC];
__device__ __nv_bfloat16 g_wp_hi[CC*CC];       // [N=1024][K=1024]
__device__ __nv_bfloat16 g_wp_lo[CC*CC];

__device__ __nv_bfloat16 g_qhi[BB*HH*TT*EE];   // [bh][t][e], pre-scaled
__device__ __nv_bfloat16 g_qlo[BB*HH*TT*EE];
__device__ __nv_bfloat16 g_khi[BB*HH*SQ*EE];   // [bh][s][e]
__device__ __nv_bfloat16 g_klo[BB*HH*SQ*EE];
__device__ __nv_bfloat16 g_vthi[BB*HH*EE*SQ];  // [bh][e][s] (transposed)
__device__ __nv_bfloat16 g_vtlo[BB*HH*EE*SQ];

// ---------------------------------------------------------------------------
// Helpers
// ---------------------------------------------------------------------------
__device__ __forceinline__ void mma16816(float c[4],
    uint32_t a0, uint32_t a1, uint32_t a2, uint32_t a3,
    uint32_t b0, uint32_t b1)
{
    asm volatile(
        "mma.sync.aligned.m16n8k16.row.col.f32.bf16.bf16.f32 "
        "{%0,%1,%2,%3}, {%4,%5,%6,%7}, {%8,%9}, {%0,%1,%2,%3};"
        : "+f"(c[0]), "+f"(c[1]), "+f"(c[2]), "+f"(c[3])
        : "r"(a0), "r"(a1), "r"(a2), "r"(a3), "r"(b0), "r"(b1));
}
__device__ __forceinline__ void ldm_x4(uint32_t& r0, uint32_t& r1,
                                       uint32_t& r2, uint32_t& r3, uint32_t addr)
{
    asm volatile("ldmatrix.sync.aligned.m8n8.x4.shared.b16 {%0,%1,%2,%3}, [%4];"
        : "=r"(r0), "=r"(r1), "=r"(r2), "=r"(r3) : "r"(addr));
}
__device__ __forceinline__ void cpasync16(uint32_t dst, const void* src) {
    asm volatile("cp.async.cg.shared.global [%0], [%1], 16;"
        :: "r"(dst), "l"(src) : "memory");
}
#define CP_COMMIT() asm volatile("cp.async.commit_group;" ::: "memory")
#define CP_WAIT1()  asm volatile("cp.async.wait_group 1;" ::: "memory")
#define CP_WAIT0()  asm volatile("cp.async.wait_group 0;" ::: "memory")

__device__ __forceinline__ float ex2(float x) {
    float r; asm("ex2.approx.ftz.f32 %0, %1;" : "=f"(r) : "f"(x)); return r;
}
__device__ __forceinline__ uint32_t pack_hi(float a, float b, float& ra, float& rb) {
    __nv_bfloat162 h = __floats2bfloat162_rn(a, b);
    ra = a - __low2float(h); rb = b - __high2float(h);
    return *(uint32_t*)&h;
}
__device__ __forceinline__ uint32_t pack_bf(float a, float b) {
    __nv_bfloat162 h = __floats2bfloat162_rn(a, b);
    return *(uint32_t*)&h;
}

// ---------------------------------------------------------------------------
// bf16x3 mma.sync GEMM core.
// PITCH 72 (conflict-free ldmatrix), K-chunk 64, TRIPLE-buffered cp.async.
// Single __syncthreads per chunk: prefetch target (kc+2)%3 was last read at
// chunk kc-1, which all warps completed before this chunk's top barrier.
// ---------------------------------------------------------------------------
#define PITCH 72
#define PLANE (128 * PITCH)            // halfwords per plane (9216)
#define GSTAGE (4 * PLANE)             // halfwords per stage
#define GEMM_DYN_BYTES (3 * GSTAGE * 2)   // 221184

extern __shared__ __nv_bfloat16 dyn_smem[];

__device__ __forceinline__ void tc_gemm_mma(
    const __nv_bfloat16* __restrict__ Ahi, const __nv_bfloat16* __restrict__ Alo,
    const __nv_bfloat16* __restrict__ Bhi, const __nv_bfloat16* __restrict__ Blo,
    int m0, int n0, float c[4][4][4])
{
    const int tid = threadIdx.x;
    const int wid = tid >> 5, lane = tid & 31;
    const int wm = wid & 1, wn = wid >> 1;
    const int sel = lane >> 3, r8 = lane & 7;

    #pragma unroll
    for (int i = 0; i < 4; i++)
        #pragma unroll
        for (int j = 0; j < 4; j++)
            #pragma unroll
            for (int t = 0; t < 4; t++) c[i][j][t] = 0.f;

    const uint32_t sbase = (uint32_t)__cvta_generic_to_shared(dyn_smem);
    const __nv_bfloat16* planes[4] = {Ahi, Alo, Bhi, Blo};

    auto prefetch = [&](int kc, int buf) {
        const int k0 = kc * 64;
        #pragma unroll
        for (int p = 0; p < 4; p++) {
            const __nv_bfloat16* src = planes[p];
            const int br = (p < 2) ? m0 : n0;
            const uint32_t dplane = sbase + (uint32_t)(buf * GSTAGE + p * PLANE) * 2;
            #pragma unroll
            for (int i = 0; i < 4; i++) {
                const int idx = i * 256 + tid;        // [0,1024)
                const int row = idx >> 3, seg = idx & 7;
                cpasync16(dplane + (uint32_t)(row * PITCH + seg * 8) * 2,
                          src + (size_t)(br + row) * 1024 + k0 + seg * 8);
            }
        }
        CP_COMMIT();
    };

    prefetch(0, 0);
    prefetch(1, 1);

    for (int kc = 0; kc < 16; kc++) {
        const int buf = kc % 3;
        if (kc == 15) { CP_WAIT0(); } else { CP_WAIT1(); }
        __syncthreads();

        const uint32_t ab  = sbase + (uint32_t)(buf * GSTAGE) * 2;
        const uint32_t pAh = ab;
        const uint32_t pAl = ab + (uint32_t)PLANE * 2;
        const uint32_t pBh = ab + (uint32_t)(2 * PLANE) * 2;
        const uint32_t pBl = ab + (uint32_t)(3 * PLANE) * 2;

        #pragma unroll
        for (int k16 = 0; k16 < 4; k16++) {
            const int kb = k16 * 16;
            uint32_t aH[4][4], aL[4][4], bH[2][4], bL[2][4];
            #pragma unroll
            for (int i = 0; i < 4; i++) {
                const uint32_t off = (uint32_t)((wm * 64 + i * 16 + r8 + (sel & 1) * 8) * PITCH
                                                + kb + (sel >> 1) * 8) * 2;
                ldm_x4(aH[i][0], aH[i][1], aH[i][2], aH[i][3], pAh + off);
                ldm_x4(aL[i][0], aL[i][1], aL[i][2], aL[i][3], pAl + off);
            }
            #pragma unroll
            for (int jp = 0; jp < 2; jp++) {
                const uint32_t off = (uint32_t)(((wn * 32 + (jp * 2 + (sel >> 1)) * 8) + r8) * PITCH
                                                + kb + (sel & 1) * 8) * 2;
                ldm_x4(bH[jp][0], bH[jp][1], bH[jp][2], bH[jp][3], pBh + off);
                ldm_x4(bL[jp][0], bL[jp][1], bL[jp][2], bL[jp][3], pBl + off);
            }
            #pragma unroll
            for (int i = 0; i < 4; i++)
                #pragma unroll
                for (int j = 0; j < 4; j++) {
                    const uint32_t b0h = bH[j >> 1][(j & 1) * 2];
                    const uint32_t b1h = bH[j >> 1][(j & 1) * 2 + 1];
                    const uint32_t b0l = bL[j >> 1][(j & 1) * 2];
                    const uint32_t b1l = bL[j >> 1][(j & 1) * 2 + 1];
                    mma16816(c[i][j], aH[i][0], aH[i][1], aH[i][2], aH[i][3], b0h, b1h);
                    mma16816(c[i][j], aH[i][0], aH[i][1], aH[i][2], aH[i][3], b0l, b1l);
                    mma16816(c[i][j], aL[i][0], aL[i][1], aL[i][2], aL[i][3], b0h, b1h);
                }
        }
        if (kc + 2 < 16) prefetch(kc + 2, (kc + 2) % 3);
    }
}

// ---------------------------------------------------------------------------
// QKV GEMM: epilogue writes pre-scaled bf16-split q, k (seq offset 2048),
// v transposed — exactly the layouts the attention kernel consumes.
// ---------------------------------------------------------------------------
__global__ __launch_bounds__(256) void qkv_mma_kernel(const float* __restrict__ bias)
{
    const int m0 = blockIdx.y * 128, n0 = blockIdx.x * 128;
    float c[4][4][4];
    tc_gemm_mma(g_xhi, g_xlo, g_wqkv_hi, g_wqkv_lo, m0, n0, c);

    const int tid = threadIdx.x, wid = tid >> 5, lane = tid & 31;
    const int wm = wid & 1, wn = wid >> 1;
    const int qr = lane >> 2, qc = lane & 3;

    #pragma unroll
    for (int i = 0; i < 4; i++) {
        #pragma unroll
        for (int j = 0; j < 4; j++) {
            const int n = n0 + wn * 32 + j * 8 + qc * 2;
            const int part = n >> 10;
            const int h = (n & 1023) >> 6;
            const int e = n & 63;
            const float b0 = bias[n], b1 = bias[n + 1];
            #pragma unroll
            for (int half = 0; half < 2; half++) {
                const int m = m0 + wm * 64 + i * 16 + qr + half * 8;
                const int bb = m >> 9, t = m & 511;
                const int bh = bb * HH + h;
                float v0 = c[i][j][half * 2] + b0;
                float v1 = c[i][j][half * 2 + 1] + b1;
                if (part == 0) {
                    v0 *= QSCALE; v1 *= QSCALE;
                    float l0, l1;
                    uint32_t hi = pack_hi(v0, v1, l0, l1);
                    uint32_t lo = pack_bf(l0, l1);
                    size_t off = ((size_t)bh * TT + t) * 64 + e;
                    *(uint32_t*)(g_qhi + off) = hi;
                    *(uint32_t*)(g_qlo + off) = lo;
                } else if (part == 1) {
                    float l0, l1;
                    uint32_t hi = pack_hi(v0, v1, l0, l1);
                    uint32_t lo = pack_bf(l0, l1);
                    size_t off = ((size_t)bh * SQ + LL + t) * 64 + e;
                    *(uint32_t*)(g_khi + off) = hi;
                    *(uint32_t*)(g_klo + off) = lo;
                } else {
                    __nv_bfloat16 h0 = __float2bfloat16_rn(v0);
                    __nv_bfloat16 h1 = __float2bfloat16_rn(v1);
                    __nv_bfloat16 l0 = __float2bfloat16_rn(v0 - __bfloat162float(h0));
                    __nv_bfloat16 l1 = __float2bfloat16_rn(v1 - __bfloat162float(h1));
                    size_t o0 = ((size_t)bh * 64 + e) * SQ + LL + t;
                    size_t o1 = ((size_t)bh * 64 + e + 1) * SQ + LL + t;
                    g_vthi[o0] = h0; g_vtlo[o0] = l0;
                    g_vthi[o1] = h1; g_vtlo[o1] = l1;
                }
            }
        }
    }
}

// ---------------------------------------------------------------------------
// Proj GEMM
// ---------------------------------------------------------------------------
__global__ __launch_bounds__(256) void proj_mma_kernel(const float* __restrict__ bias,
                                                       float* __restrict__ out)
{
    const int m0 = blockIdx.y * 128, n0 = blockIdx.x * 128;
    float c[4][4][4];
    tc_gemm_mma(g_yhi, g_ylo, g_wp_hi, g_wp_lo, m0, n0, c);

    const int tid = threadIdx.x, wid = tid >> 5, lane = tid & 31;
    const int wm = wid & 1, wn = wid >> 1;
    const int qr = lane >> 2, qc = lane & 3;

    #pragma unroll
    for (int i = 0; i < 4; i++) {
        #pragma unroll
        for (int j = 0; j < 4; j++) {
            const int n = n0 + wn * 32 + j * 8 + qc * 2;
            const float b0 = bias[n], b1 = bias[n + 1];
            #pragma unroll
            for (int half = 0; half < 2; half++) {
                const int m = m0 + wm * 64 + i * 16 + qr + half * 8;
                float2 w = make_float2(c[i][j][half * 2] + b0,
                                       c[i][j][half * 2 + 1] + b1);
                *(float2*)&out[(size_t)m * 1024 + n] = w;
            }
        }
    }
}

// ---------------------------------------------------------------------------
// Flash attention (R7 body): resident Q hi/lo fragments, resident P pack,
// TRIPLE-buffered K/V tiles, single __syncthreads per tile.
// ---------------------------------------------------------------------------
#define APITCH 72
#define APLANE (64 * APITCH)           // halfwords per array
#define ASTAGE (4 * APLANE)            // Kh,Kl,Vh,Vl
#define ATT_DYN_BYTES (3 * ASTAGE * 2) // 110592

__global__ __launch_bounds__(256) void attn_mma_kernel()
{
    const int tid = threadIdx.x, wid = tid >> 5, lane = tid & 31;
    const int l4 = lane >> 2, qn = lane & 3;
    const int sel = lane >> 3, r8 = lane & 7;
    const int bh = blockIdx.y;
    const int qb = 3 - blockIdx.x;
    const int base = qb * 128;

    const uint32_t sbase = (uint32_t)__cvta_generic_to_shared(dyn_smem);

    // Persistent Q fragments (pre-scaled bf16 hi/lo)
    uint32_t aQh[4][4], aQl[4][4];
    {
        const __nv_bfloat16* qh = g_qhi + ((size_t)bh * TT + base + wid * 16) * 64;
        const __nv_bfloat16* ql = g_qlo + ((size_t)bh * TT + base + wid * 16) * 64;
        #pragma unroll
        for (int kk = 0; kk < 4; kk++) {
            const int c0 = kk * 16 + qn * 2;
            aQh[kk][0] = *(const uint32_t*)(qh + l4 * 64 + c0);
            aQh[kk][1] = *(const uint32_t*)(qh + (l4 + 8) * 64 + c0);
            aQh[kk][2] = *(const uint32_t*)(qh + l4 * 64 + c0 + 8);
            aQh[kk][3] = *(const uint32_t*)(qh + (l4 + 8) * 64 + c0 + 8);
            aQl[kk][0] = *(const uint32_t*)(ql + l4 * 64 + c0);
            aQl[kk][1] = *(const uint32_t*)(ql + (l4 + 8) * 64 + c0);
            aQl[kk][2] = *(const uint32_t*)(ql + l4 * 64 + c0 + 8);
            aQl[kk][3] = *(const uint32_t*)(ql + (l4 + 8) * 64 + c0 + 8);
        }
    }

    float O[8][4];
    #pragma unroll
    for (int j = 0; j < 8; j++)
        #pragma unroll
        for (int t = 0; t < 4; t++) O[j][t] = 0.f;
    float mrow[2] = {-1e30f, -1e30f};
    float lrow[2] = {0.f, 0.f};

    const __nv_bfloat16* Kh  = g_khi  + (size_t)bh * SQ * 64;
    const __nv_bfloat16* Kl  = g_klo  + (size_t)bh * SQ * 64;
    const __nv_bfloat16* Vth = g_vthi + (size_t)bh * 64 * SQ;
    const __nv_bfloat16* Vtl = g_vtlo + (size_t)bh * 64 * SQ;

    const int n_tiles = 32 + 2 * (qb + 1);

    auto prefetch = [&](int kt, int buf) {
        const int s0 = kt * 64;
        const uint32_t dst = sbase + (uint32_t)(buf * ASTAGE) * 2;
        #pragma unroll
        for (int i = 0; i < 2; i++) {
            const int idx = i * 256 + tid;        // [0,512)
            const int row = idx >> 3, seg = idx & 7;
            const uint32_t doff = (uint32_t)(row * APITCH + seg * 8) * 2;
            cpasync16(dst + doff,
                      Kh + (size_t)(s0 + row) * 64 + seg * 8);
            cpasync16(dst + (uint32_t)APLANE * 2 + doff,
                      Kl + (size_t)(s0 + row) * 64 + seg * 8);
            cpasync16(dst + (uint32_t)(2 * APLANE) * 2 + doff,
                      Vth + (size_t)row * SQ + s0 + seg * 8);
            cpasync16(dst + (uint32_t)(3 * APLANE) * 2 + doff,
                      Vtl + (size_t)row * SQ + s0 + seg * 8);
        }
        CP_COMMIT();
    };

    prefetch(0, 0);
    if (n_tiles > 1) prefetch(1, 1);

    for (int kt = 0; kt < n_tiles; kt++) {
        const int buf = kt % 3;
        if (kt >= n_tiles - 1) { CP_WAIT0(); } else { CP_WAIT1(); }
        __syncthreads();

        const uint32_t ab  = sbase + (uint32_t)(buf * ASTAGE) * 2;
        const uint32_t pKh = ab;
        const uint32_t pKl = ab + (uint32_t)APLANE * 2;
        const uint32_t pVh = ab + (uint32_t)(2 * APLANE) * 2;
        const uint32_t pVl = ab + (uint32_t)(3 * APLANE) * 2;
        const int s0 = kt * 64;

        // S = Q K^T (bf16x3)
        float Sc[8][4];
        #pragma unroll
        for (int j = 0; j < 8; j++)
            #pragma unroll
            for (int t = 0; t < 4; t++) Sc[j][t] = 0.f;

        #pragma unroll
        for (int kk = 0; kk < 4; kk++) {
            #pragma unroll
            for (int jp = 0; jp < 4; jp++) {
                const uint32_t off = (uint32_t)(((jp * 2 + (sel >> 1)) * 8 + r8) * APITCH
                                                + kk * 16 + (sel & 1) * 8) * 2;
                uint32_t kh[4], kl[4];
                ldm_x4(kh[0], kh[1], kh[2], kh[3], pKh + off);
                ldm_x4(kl[0], kl[1], kl[2], kl[3], pKl + off);
                #pragma unroll
                for (int jj = 0; jj < 2; jj++) {
                    const int j = jp * 2 + jj;
                    mma16816(Sc[j], aQh[kk][0], aQh[kk][1], aQh[kk][2], aQh[kk][3],
                             kh[jj * 2], kh[jj * 2 + 1]);
                    mma16816(Sc[j], aQh[kk][0], aQh[kk][1], aQh[kk][2], aQh[kk][3],
                             kl[jj * 2], kl[jj * 2 + 1]);
                    mma16816(Sc[j], aQl[kk][0], aQl[kk][1], aQl[kk][2], aQl[kk][3],
                             kh[jj * 2], kh[jj * 2 + 1]);
                }
            }
        }

        // Causal mask (block-local query row)
        if (kt >= n_tiles - 2) {
            const int lim = s0 - LL - base;
            #pragma unroll
            for (int j = 0; j < 8; j++)
                #pragma unroll
                for (int t = 0; t < 4; t++) {
                    const int col = j * 8 + qn * 2 + (t & 1);
                    const int row = wid * 16 + l4 + ((t >> 1) << 3);
                    if (col + lim > row) Sc[j][t] = -1e30f;
                }
        }

        // Online softmax (per row-half; 4-lane shfl reductions)
        #pragma unroll
        for (int h = 0; h < 2; h++) {
            float mt = -1e30f;
            #pragma unroll
            for (int j = 0; j < 8; j++)
                mt = fmaxf(mt, fmaxf(Sc[j][2 * h], Sc[j][2 * h + 1]));
            mt = fmaxf(mt, __shfl_xor_sync(0xffffffffu, mt, 1));
            mt = fmaxf(mt, __shfl_xor_sync(0xffffffffu, mt, 2));
            const float mn = fmaxf(mrow[h], mt);
            const float alpha = ex2(mrow[h] - mn);
            mrow[h] = mn;
            float ls = 0.f;
            #pragma unroll
            for (int j = 0; j < 8; j++) {
                float p0 = ex2(Sc[j][2 * h] - mn);
                float p1 = ex2(Sc[j][2 * h + 1] - mn);
                Sc[j][2 * h] = p0; Sc[j][2 * h + 1] = p1;
                ls += p0 + p1;
            }
            ls += __shfl_xor_sync(0xffffffffu, ls, 1);
            ls += __shfl_xor_sync(0xffffffffu, ls, 2);
            lrow[h] = lrow[h] * alpha + ls;
            #pragma unroll
            for (int j = 0; j < 8; j++) {
                O[j][2 * h] *= alpha; O[j][2 * h + 1] *= alpha;
            }
        }

        // Pack P -> A fragments (register-only; layouts match)
        uint32_t aPh[4][4], aPl[4][4];
        #pragma unroll
        for (int kk = 0; kk < 4; kk++) {
            const int j0 = 2 * kk, j1 = 2 * kk + 1;
            float l0, l1;
            aPh[kk][0] = pack_hi(Sc[j0][0], Sc[j0][1], l0, l1);
            aPl[kk][0] = pack_bf(l0, l1);
            aPh[kk][1] = pack_hi(Sc[j0][2], Sc[j0][3], l0, l1);
            aPl[kk][1] = pack_bf(l0, l1);
            aPh[kk][2] = pack_hi(Sc[j1][0], Sc[j1][1], l0, l1);
            aPl[kk][2] = pack_bf(l0, l1);
            aPh[kk][3] = pack_hi(Sc[j1][2], Sc[j1][3], l0, l1);
            aPl[kk][3] = pack_bf(l0, l1);
        }

        // O += P V (bf16x3; V^T as B)
        #pragma unroll
        for (int kk = 0; kk < 4; kk++) {
            #pragma unroll
            for (int jp = 0; jp < 4; jp++) {
                const uint32_t off = (uint32_t)(((jp * 2 + (sel >> 1)) * 8 + r8) * APITCH
                                                + kk * 16 + (sel & 1) * 8) * 2;
                uint32_t vh[4], vl[4];
                ldm_x4(vh[0], vh[1], vh[2], vh[3], pVh + off);
                ldm_x4(vl[0], vl[1], vl[2], vl[3], pVl + off);
                #pragma unroll
                for (int jj = 0; jj < 2; jj++) {
                    const int j = jp * 2 + jj;
                    mma16816(O[j], aPh[kk][0], aPh[kk][1], aPh[kk][2], aPh[kk][3],
                             vh[jj * 2], vh[jj * 2 + 1]);
                    mma16816(O[j], aPh[kk][0], aPh[kk][1], aPh[kk][2], aPh[kk][3],
                             vl[jj * 2], vl[jj * 2 + 1]);
                    mma16816(O[j], aPl[kk][0], aPl[kk][1], aPl[kk][2], aPl[kk][3],
                             vh[jj * 2], vh[jj * 2 + 1]);
                }
            }
        }

        if (kt + 2 < n_tiles) prefetch(kt + 2, (kt + 2) % 3);
    }

    // Epilogue: y = O / l -> bf16-split proj input
    const int b = bh >> 4, hh = bh & 15;
    #pragma unroll
    for (int h = 0; h < 2; h++) {
        const int t = base + wid * 16 + l4 + h * 8;
        const float inv = 1.f / lrow[h];
        #pragma unroll
        for (int j = 0; j < 8; j++) {
            const float y0 = O[j][2 * h] * inv;
            const float y1 = O[j][2 * h + 1] * inv;
            float l0, l1;
            uint32_t hi = pack_hi(y0, y1, l0, l1);
            uint32_t lo = pack_bf(l0, l1);
            const size_t off = ((size_t)(b * TT + t)) * CC + hh * 64 + j * 8 + qn * 2;
            *(uint32_t*)(g_yhi + off) = hi;
            *(uint32_t*)(g_ylo + off) = lo;
        }
    }
}

// ---------------------------------------------------------------------------
// Fused prep kernel: one launch covers x-split, both weight transposes,
// and both KV-cache conversions. All regions use 256-thread blocks.
//   [0, 4096)          x split
//   [4096, 7168)       Wqkv transpose-split  (96 x 32 tiles)
//   [7168, 8192)       Wproj transpose-split (32 x 32 tiles)
//   [8192, 24576)      K-cache convert
//   [24576, 40960)     V-cache transpose-convert (64 x 2 x 128 tiles)
// ---------------------------------------------------------------------------
#define NB_XS 4096
#define NB_WQ 3072
#define NB_WP 1024
#define NB_KC 16384
#define NB_VC 16384
#define NB_TOTAL (NB_XS + NB_WQ + NB_WP + NB_KC + NB_VC)

__global__ __launch_bounds__(256) void prep_fused(
    const float* __restrict__ x,
    const float* __restrict__ kc,
    const float* __restrict__ vc,
    const float* __restrict__ Wqkv,
    const float* __restrict__ Wproj)
{
    __shared__ float tile[32][33];
    const int bid = blockIdx.x;
    const int tid = threadIdx.x;

    if (bid < NB_XS) {
        // ---- x split ----
        const int i = bid * 256 + tid;            // float4 index < 1048576
        float4 v = ((const float4*)x)[i];
        __nv_bfloat16 hh[4], ll[4];
        float a[4] = {v.x, v.y, v.z, v.w};
        #pragma unroll
        for (int j = 0; j < 4; j++) {
            hh[j] = __float2bfloat16_rn(a[j]);
            ll[j] = __float2bfloat16_rn(a[j] - __bfloat162float(hh[j]));
        }
        ((uint2*)g_xhi)[i] = *(uint2*)hh;
        ((uint2*)g_xlo)[i] = *(uint2*)ll;
    } else if (bid < NB_XS + NB_WQ + NB_WP) {
        // ---- weight transpose-split ----
        const float* W;
        __nv_bfloat16 *hi, *lo;
        int f, N;
        if (bid < NB_XS + NB_WQ) {
            f = bid - NB_XS; W = Wqkv; hi = g_wqkv_hi; lo = g_wqkv_lo; N = 3072;
        } else {
            f = bid - NB_XS - NB_WQ; W = Wproj; hi = g_wp_hi; lo = g_wp_lo; N = 1024;
        }
        const int ntx = N / 32;
        const int nx = (f % ntx) * 32, kx = (f / ntx) * 32;
        const int tx = tid & 31, ty = tid >> 5;
        #pragma unroll
        for (int r = ty; r < 32; r += 8)
            tile[r][tx] = W[(size_t)(kx + r) * N + nx + tx];
        __syncthreads();
        #pragma unroll
        for (int r = ty; r < 32; r += 8) {
            float xx = tile[tx][r];               // = W[kx+tx][nx+r]
            __nv_bfloat16 h = __float2bfloat16_rn(xx);
            __nv_bfloat16 l = __float2bfloat16_rn(xx - __bfloat162float(h));
            size_t o = (size_t)(nx + r) * 1024 + kx + tx;
            hi[o] = h;
            lo[o] = l;
        }
    } else if (bid < NB_XS + NB_WQ + NB_WP + NB_KC) {
        // ---- K cache ----
        const size_t i = (size_t)(bid - NB_XS - NB_WQ - NB_WP) * 256 + tid;
        float4 v = ((const float4*)kc)[i];
        const size_t flat = i * 4;
        const size_t bh = flat >> 17;
        const size_t rem = flat & 131071;
        const size_t s = rem >> 6, e = rem & 63;
        __nv_bfloat16 hh[4], ll[4];
        float a[4] = {v.x, v.y, v.z, v.w};
        #pragma unroll
        for (int j = 0; j < 4; j++) {
            hh[j] = __float2bfloat16_rn(a[j]);
            ll[j] = __float2bfloat16_rn(a[j] - __bfloat162float(hh[j]));
        }
        const size_t off = (bh * SQ + s) * 64 + e;
        *(uint2*)(g_khi + off) = *(uint2*)hh;
        *(uint2*)(g_klo + off) = *(uint2*)ll;
    } else {
        // ---- V cache transpose-convert ----
        const int f = bid - NB_XS - NB_WQ - NB_WP - NB_KC;   // [0, 16384)
        const int sx = f & 63;           // s-tile
        const int ey = (f >> 6) & 1;     // e-tile
        const int bh = f >> 7;           // [0,128)
        const int s0 = sx * 32, e0 = ey * 32;
        const int tx = tid & 31, ty = tid >> 5;
        #pragma unroll
        for (int r = ty; r < 32; r += 8)
            tile[r][tx] = vc[((size_t)bh * LL + s0 + r) * 64 + e0 + tx];
        __syncthreads();
        #pragma unroll
        for (int r = ty; r < 32; r += 8) {
            float xx = tile[tx][r];   // = vc[bh][s0+tx][e0+r]
            __nv_bfloat16 h = __float2bfloat16_rn(xx);
            __nv_bfloat16 l = __float2bfloat16_rn(xx - __bfloat162float(h));
            const size_t off = ((size_t)bh * 64 + e0 + r) * SQ + s0 + tx;
            g_vthi[off] = h;
            g_vtlo[off] = l;
        }
    }
}

// ---------------------------------------------------------------------------
extern "C" void kernel_launch(void* const* d_in, const int* in_sizes, int n_in,
                              void* d_out, int out_size) {
    const float* x       = (const float*)d_in[0];
    const float* k_cache = (const float*)d_in[1];
    const float* v_cache = (const float*)d_in[2];
    const float* Wqkv    = (const float*)d_in[3];
    const float* bqkv    = (const float*)d_in[4];
    const float* Wproj   = (const float*)d_in[5];
    const float* bproj   = (const float*)d_in[6];
    float* out           = (float*)d_out;

    cudaFuncSetAttribute(qkv_mma_kernel, cudaFuncAttributeMaxDynamicSharedMemorySize,
                         GEMM_DYN_BYTES);
    cudaFuncSetAttribute(proj_mma_kernel, cudaFuncAttributeMaxDynamicSharedMemorySize,
                         GEMM_DYN_BYTES);
    cudaFuncSetAttribute(attn_mma_kernel, cudaFuncAttributeMaxDynamicSharedMemorySize,
                         ATT_DYN_BYTES);

    prep_fused<<<NB_TOTAL, 256>>>(x, k_cache, v_cache, Wqkv, Wproj);

    qkv_mma_kernel<<<dim3(24, 32), 256, GEMM_DYN_BYTES>>>(bqkv);
    attn_mma_kernel<<<dim3(4, 128), 256, ATT_DYN_BYTES>>>();
    proj_mma_kernel<<<dim3(8, 32), 256, GEMM_DYN_BYTES>>>(bproj, out);
}

// round 10
// speedup vs baseline: 1.4489x; 1.4489x over previous
#include <cuda_runtime.h>
#include <cuda_bf16.h>
#include <cstdint>
#include <math.h>

#define BB 8
#define TT 512
#define CC 1024
#define HH 16
#define EE 64
#define LL 2048
#define SQ 2560                     // L + T
#define QSCALE 0.1803368801111244f  // 0.125 * log2(e)

// ---------------------------------------------------------------------------
// Scratch (__device__ globals; no allocation allowed)
// ---------------------------------------------------------------------------
__device__ __nv_bfloat16 g_xhi[BB*TT*CC];
__device__ __nv_bfloat16 g_xlo[BB*TT*CC];
__device__ __nv_bfloat16 g_yhi[BB*TT*CC];
__device__ __nv_bfloat16 g_ylo[BB*TT*CC];
__device__ __nv_bfloat16 g_wqkv_hi[3*CC*CC];   // [N=3072][K=1024]
__device__ __nv_bfloat16 g_wqkv_lo[3*CC*CC];
__device__ __nv_bfloat16 g_wp_hi[CC*CC];       // [N=1024][K=1024]
__device__ __nv_bfloat16 g_wp_lo[CC*CC];

__device__ __nv_bfloat16 g_qhi[BB*HH*TT*EE];   // [bh][t][e], pre-scaled
__device__ __nv_bfloat16 g_qlo[BB*HH*TT*EE];
__device__ __nv_bfloat16 g_khi[BB*HH*SQ*EE];   // [bh][s][e]
__device__ __nv_bfloat16 g_klo[BB*HH*SQ*EE];
__device__ __nv_bfloat16 g_vthi[BB*HH*EE*SQ];  // [bh][e][s] (transposed)
__device__ __nv_bfloat16 g_vtlo[BB*HH*EE*SQ];

// ---------------------------------------------------------------------------
// Helpers
// ---------------------------------------------------------------------------
__device__ __forceinline__ void mma16816(float c[4],
    uint32_t a0, uint32_t a1, uint32_t a2, uint32_t a3,
    uint32_t b0, uint32_t b1)
{
    asm volatile(
        "mma.sync.aligned.m16n8k16.row.col.f32.bf16.bf16.f32 "
        "{%0,%1,%2,%3}, {%4,%5,%6,%7}, {%8,%9}, {%0,%1,%2,%3};"
        : "+f"(c[0]), "+f"(c[1]), "+f"(c[2]), "+f"(c[3])
        : "r"(a0), "r"(a1), "r"(a2), "r"(a3), "r"(b0), "r"(b1));
}
__device__ __forceinline__ void ldm_x4(uint32_t& r0, uint32_t& r1,
                                       uint32_t& r2, uint32_t& r3, uint32_t addr)
{
    asm volatile("ldmatrix.sync.aligned.m8n8.x4.shared.b16 {%0,%1,%2,%3}, [%4];"
        : "=r"(r0), "=r"(r1), "=r"(r2), "=r"(r3) : "r"(addr));
}
__device__ __forceinline__ void cpasync16(uint32_t dst, const void* src) {
    asm volatile("cp.async.cg.shared.global [%0], [%1], 16;"
        :: "r"(dst), "l"(src) : "memory");
}
#define CP_COMMIT() asm volatile("cp.async.commit_group;" ::: "memory")
#define CP_WAIT1()  asm volatile("cp.async.wait_group 1;" ::: "memory")
#define CP_WAIT0()  asm volatile("cp.async.wait_group 0;" ::: "memory")

__device__ __forceinline__ float ex2(float x) {
    float r; asm("ex2.approx.ftz.f32 %0, %1;" : "=f"(r) : "f"(x)); return r;
}
__device__ __forceinline__ uint32_t pack_hi(float a, float b, float& ra, float& rb) {
    __nv_bfloat162 h = __floats2bfloat162_rn(a, b);
    ra = a - __low2float(h); rb = b - __high2float(h);
    return *(uint32_t*)&h;
}
__device__ __forceinline__ uint32_t pack_bf(float a, float b) {
    __nv_bfloat162 h = __floats2bfloat162_rn(a, b);
    return *(uint32_t*)&h;
}

// ---------------------------------------------------------------------------
// bf16x3 mma.sync GEMM core (796.6us configuration):
// PITCH 40, K-chunk 32, double-buffered cp.async, two syncs per chunk.
// ---------------------------------------------------------------------------
#define PITCH 40
#define PLANE (128 * PITCH)            // halfwords per plane
#define GSTAGE (4 * PLANE)             // halfwords per stage
#define GEMM_DYN_BYTES (2 * GSTAGE * 2)   // 81920

extern __shared__ __nv_bfloat16 dyn_smem[];

__device__ __forceinline__ void tc_gemm_mma(
    const __nv_bfloat16* __restrict__ Ahi, const __nv_bfloat16* __restrict__ Alo,
    const __nv_bfloat16* __restrict__ Bhi, const __nv_bfloat16* __restrict__ Blo,
    int m0, int n0, float c[4][4][4])
{
    const int tid = threadIdx.x;
    const int wid = tid >> 5, lane = tid & 31;
    const int wm = wid & 1, wn = wid >> 1;
    const int sel = lane >> 3, r8 = lane & 7;

    #pragma unroll
    for (int i = 0; i < 4; i++)
        #pragma unroll
        for (int j = 0; j < 4; j++)
            #pragma unroll
            for (int t = 0; t < 4; t++) c[i][j][t] = 0.f;

    const uint32_t sbase = (uint32_t)__cvta_generic_to_shared(dyn_smem);
    const __nv_bfloat16* planes[4] = {Ahi, Alo, Bhi, Blo};

    auto prefetch = [&](int kc, int buf) {
        const int k0 = kc * 32;
        #pragma unroll
        for (int p = 0; p < 4; p++) {
            const __nv_bfloat16* src = planes[p];
            const int br = (p < 2) ? m0 : n0;
            const uint32_t dplane = sbase + (uint32_t)(buf * GSTAGE + p * PLANE) * 2;
            #pragma unroll
            for (int i = 0; i < 2; i++) {
                const int idx = i * 256 + tid;        // [0,512)
                const int row = idx >> 2, seg = idx & 3;
                cpasync16(dplane + (uint32_t)(row * PITCH + seg * 8) * 2,
                          src + (size_t)(br + row) * 1024 + k0 + seg * 8);
            }
        }
        CP_COMMIT();
    };

    prefetch(0, 0);
    prefetch(1, 1);

    for (int kc = 0; kc < 32; kc++) {
        const int buf = kc & 1;
        if (kc == 31) { CP_WAIT0(); } else { CP_WAIT1(); }
        __syncthreads();

        const uint32_t ab  = sbase + (uint32_t)(buf * GSTAGE) * 2;
        const uint32_t pAh = ab;
        const uint32_t pAl = ab + (uint32_t)PLANE * 2;
        const uint32_t pBh = ab + (uint32_t)(2 * PLANE) * 2;
        const uint32_t pBl = ab + (uint32_t)(3 * PLANE) * 2;

        #pragma unroll
        for (int k16 = 0; k16 < 2; k16++) {
            const int kb = k16 * 16;
            uint32_t aH[4][4], aL[4][4], bH[2][4], bL[2][4];
            #pragma unroll
            for (int i = 0; i < 4; i++) {
                const uint32_t off = (uint32_t)((wm * 64 + i * 16 + r8 + (sel & 1) * 8) * PITCH
                                                + kb + (sel >> 1) * 8) * 2;
                ldm_x4(aH[i][0], aH[i][1], aH[i][2], aH[i][3], pAh + off);
                ldm_x4(aL[i][0], aL[i][1], aL[i][2], aL[i][3], pAl + off);
            }
            #pragma unroll
            for (int jp = 0; jp < 2; jp++) {
                const uint32_t off = (uint32_t)(((wn * 32 + (jp * 2 + (sel >> 1)) * 8) + r8) * PITCH
                                                + kb + (sel & 1) * 8) * 2;
                ldm_x4(bH[jp][0], bH[jp][1], bH[jp][2], bH[jp][3], pBh + off);
                ldm_x4(bL[jp][0], bL[jp][1], bL[jp][2], bL[jp][3], pBl + off);
            }
            #pragma unroll
            for (int i = 0; i < 4; i++)
                #pragma unroll
                for (int j = 0; j < 4; j++) {
                    const uint32_t b0h = bH[j >> 1][(j & 1) * 2];
                    const uint32_t b1h = bH[j >> 1][(j & 1) * 2 + 1];
                    const uint32_t b0l = bL[j >> 1][(j & 1) * 2];
                    const uint32_t b1l = bL[j >> 1][(j & 1) * 2 + 1];
                    mma16816(c[i][j], aH[i][0], aH[i][1], aH[i][2], aH[i][3], b0h, b1h);
                    mma16816(c[i][j], aH[i][0], aH[i][1], aH[i][2], aH[i][3], b0l, b1l);
                    mma16816(c[i][j], aL[i][0], aL[i][1], aL[i][2], aL[i][3], b0h, b1h);
                }
        }
        __syncthreads();
        if (kc + 2 < 32) prefetch(kc + 2, buf);
    }
}

// ---------------------------------------------------------------------------
// QKV GEMM: epilogue writes pre-scaled bf16-split q, k (seq offset 2048),
// v transposed — exactly the layouts the attention kernel consumes.
// ---------------------------------------------------------------------------
__global__ __launch_bounds__(256) void qkv_mma_kernel(const float* __restrict__ bias)
{
    const int m0 = blockIdx.y * 128, n0 = blockIdx.x * 128;
    float c[4][4][4];
    tc_gemm_mma(g_xhi, g_xlo, g_wqkv_hi, g_wqkv_lo, m0, n0, c);

    const int tid = threadIdx.x, wid = tid >> 5, lane = tid & 31;
    const int wm = wid & 1, wn = wid >> 1;
    const int qr = lane >> 2, qc = lane & 3;

    #pragma unroll
    for (int i = 0; i < 4; i++) {
        #pragma unroll
        for (int j = 0; j < 4; j++) {
            const int n = n0 + wn * 32 + j * 8 + qc * 2;
            const int part = n >> 10;
            const int h = (n & 1023) >> 6;
            const int e = n & 63;
            const float b0 = bias[n], b1 = bias[n + 1];
            #pragma unroll
            for (int half = 0; half < 2; half++) {
                const int m = m0 + wm * 64 + i * 16 + qr + half * 8;
                const int bb = m >> 9, t = m & 511;
                const int bh = bb * HH + h;
                float v0 = c[i][j][half * 2] + b0;
                float v1 = c[i][j][half * 2 + 1] + b1;
                if (part == 0) {
                    v0 *= QSCALE; v1 *= QSCALE;
                    float l0, l1;
                    uint32_t hi = pack_hi(v0, v1, l0, l1);
                    uint32_t lo = pack_bf(l0, l1);
                    size_t off = ((size_t)bh * TT + t) * 64 + e;
                    *(uint32_t*)(g_qhi + off) = hi;
                    *(uint32_t*)(g_qlo + off) = lo;
                } else if (part == 1) {
                    float l0, l1;
                    uint32_t hi = pack_hi(v0, v1, l0, l1);
                    uint32_t lo = pack_bf(l0, l1);
                    size_t off = ((size_t)bh * SQ + LL + t) * 64 + e;
                    *(uint32_t*)(g_khi + off) = hi;
                    *(uint32_t*)(g_klo + off) = lo;
                } else {
                    __nv_bfloat16 h0 = __float2bfloat16_rn(v0);
                    __nv_bfloat16 h1 = __float2bfloat16_rn(v1);
                    __nv_bfloat16 l0 = __float2bfloat16_rn(v0 - __bfloat162float(h0));
                    __nv_bfloat16 l1 = __float2bfloat16_rn(v1 - __bfloat162float(h1));
                    size_t o0 = ((size_t)bh * 64 + e) * SQ + LL + t;
                    size_t o1 = ((size_t)bh * 64 + e + 1) * SQ + LL + t;
                    g_vthi[o0] = h0; g_vtlo[o0] = l0;
                    g_vthi[o1] = h1; g_vtlo[o1] = l1;
                }
            }
        }
    }
}

// ---------------------------------------------------------------------------
// Proj GEMM
// ---------------------------------------------------------------------------
__global__ __launch_bounds__(256) void proj_mma_kernel(const float* __restrict__ bias,
                                                       float* __restrict__ out)
{
    const int m0 = blockIdx.y * 128, n0 = blockIdx.x * 128;
    float c[4][4][4];
    tc_gemm_mma(g_yhi, g_ylo, g_wp_hi, g_wp_lo, m0, n0, c);

    const int tid = threadIdx.x, wid = tid >> 5, lane = tid & 31;
    const int wm = wid & 1, wn = wid >> 1;
    const int qr = lane >> 2, qc = lane & 3;

    #pragma unroll
    for (int i = 0; i < 4; i++) {
        #pragma unroll
        for (int j = 0; j < 4; j++) {
            const int n = n0 + wn * 32 + j * 8 + qc * 2;
            const float b0 = bias[n], b1 = bias[n + 1];
            #pragma unroll
            for (int half = 0; half < 2; half++) {
                const int m = m0 + wm * 64 + i * 16 + qr + half * 8;
                float2 w = make_float2(c[i][j][half * 2] + b0,
                                       c[i][j][half * 2 + 1] + b1);
                *(float2*)&out[(size_t)m * 1024 + n] = w;
            }
        }
    }
}

// ---------------------------------------------------------------------------
// Flash attention (796.6us body): resident Q hi/lo fragments, resident P
// pack, double-buffered K/V tiles, two __syncthreads per tile.
// ---------------------------------------------------------------------------
#define APITCH 72
#define APLANE (64 * APITCH)           // halfwords per array
#define ASTAGE (4 * APLANE)            // Kh,Kl,Vh,Vl
#define ATT_DYN_BYTES (2 * ASTAGE * 2) // 73728

__global__ __launch_bounds__(256) void attn_mma_kernel()
{
    const int tid = threadIdx.x, wid = tid >> 5, lane = tid & 31;
    const int l4 = lane >> 2, qn = lane & 3;
    const int sel = lane >> 3, r8 = lane & 7;
    const int bh = blockIdx.y;
    const int qb = 3 - blockIdx.x;
    const int base = qb * 128;

    const uint32_t sbase = (uint32_t)__cvta_generic_to_shared(dyn_smem);

    // Persistent Q fragments (pre-scaled bf16 hi/lo)
    uint32_t aQh[4][4], aQl[4][4];
    {
        const __nv_bfloat16* qh = g_qhi + ((size_t)bh * TT + base + wid * 16) * 64;
        const __nv_bfloat16* ql = g_qlo + ((size_t)bh * TT + base + wid * 16) * 64;
        #pragma unroll
        for (int kk = 0; kk < 4; kk++) {
            const int c0 = kk * 16 + qn * 2;
            aQh[kk][0] = *(const uint32_t*)(qh + l4 * 64 + c0);
            aQh[kk][1] = *(const uint32_t*)(qh + (l4 + 8) * 64 + c0);
            aQh[kk][2] = *(const uint32_t*)(qh + l4 * 64 + c0 + 8);
            aQh[kk][3] = *(const uint32_t*)(qh + (l4 + 8) * 64 + c0 + 8);
            aQl[kk][0] = *(const uint32_t*)(ql + l4 * 64 + c0);
            aQl[kk][1] = *(const uint32_t*)(ql + (l4 + 8) * 64 + c0);
            aQl[kk][2] = *(const uint32_t*)(ql + l4 * 64 + c0 + 8);
            aQl[kk][3] = *(const uint32_t*)(ql + (l4 + 8) * 64 + c0 + 8);
        }
    }

    float O[8][4];
    #pragma unroll
    for (int j = 0; j < 8; j++)
        #pragma unroll
        for (int t = 0; t < 4; t++) O[j][t] = 0.f;
    float mrow[2] = {-1e30f, -1e30f};
    float lrow[2] = {0.f, 0.f};

    const __nv_bfloat16* Kh  = g_khi  + (size_t)bh * SQ * 64;
    const __nv_bfloat16* Kl  = g_klo  + (size_t)bh * SQ * 64;
    const __nv_bfloat16* Vth = g_vthi + (size_t)bh * 64 * SQ;
    const __nv_bfloat16* Vtl = g_vtlo + (size_t)bh * 64 * SQ;

    const int n_tiles = 32 + 2 * (qb + 1);

    auto prefetch = [&](int kt, int buf) {
        const int s0 = kt * 64;
        const uint32_t dst = sbase + (uint32_t)(buf * ASTAGE) * 2;
        #pragma unroll
        for (int i = 0; i < 2; i++) {
            const int idx = i * 256 + tid;        // [0,512)
            const int row = idx >> 3, seg = idx & 7;
            const uint32_t doff = (uint32_t)(row * APITCH + seg * 8) * 2;
            cpasync16(dst + doff,
                      Kh + (size_t)(s0 + row) * 64 + seg * 8);
            cpasync16(dst + (uint32_t)APLANE * 2 + doff,
                      Kl + (size_t)(s0 + row) * 64 + seg * 8);
            cpasync16(dst + (uint32_t)(2 * APLANE) * 2 + doff,
                      Vth + (size_t)row * SQ + s0 + seg * 8);
            cpasync16(dst + (uint32_t)(3 * APLANE) * 2 + doff,
                      Vtl + (size_t)row * SQ + s0 + seg * 8);
        }
        CP_COMMIT();
    };

    prefetch(0, 0);
    if (n_tiles > 1) prefetch(1, 1);

    for (int kt = 0; kt < n_tiles; kt++) {
        const int buf = kt & 1;
        if (kt >= n_tiles - 1) { CP_WAIT0(); } else { CP_WAIT1(); }
        __syncthreads();

        const uint32_t ab  = sbase + (uint32_t)(buf * ASTAGE) * 2;
        const uint32_t pKh = ab;
        const uint32_t pKl = ab + (uint32_t)APLANE * 2;
        const uint32_t pVh = ab + (uint32_t)(2 * APLANE) * 2;
        const uint32_t pVl = ab + (uint32_t)(3 * APLANE) * 2;
        const int s0 = kt * 64;

        // S = Q K^T (bf16x3)
        float Sc[8][4];
        #pragma unroll
        for (int j = 0; j < 8; j++)
            #pragma unroll
            for (int t = 0; t < 4; t++) Sc[j][t] = 0.f;

        #pragma unroll
        for (int kk = 0; kk < 4; kk++) {
            #pragma unroll
            for (int jp = 0; jp < 4; jp++) {
                const uint32_t off = (uint32_t)(((jp * 2 + (sel >> 1)) * 8 + r8) * APITCH
                                                + kk * 16 + (sel & 1) * 8) * 2;
                uint32_t kh[4], kl[4];
                ldm_x4(kh[0], kh[1], kh[2], kh[3], pKh + off);
                ldm_x4(kl[0], kl[1], kl[2], kl[3], pKl + off);
                #pragma unroll
                for (int jj = 0; jj < 2; jj++) {
                    const int j = jp * 2 + jj;
                    mma16816(Sc[j], aQh[kk][0], aQh[kk][1], aQh[kk][2], aQh[kk][3],
                             kh[jj * 2], kh[jj * 2 + 1]);
                    mma16816(Sc[j], aQh[kk][0], aQh[kk][1], aQh[kk][2], aQh[kk][3],
                             kl[jj * 2], kl[jj * 2 + 1]);
                    mma16816(Sc[j], aQl[kk][0], aQl[kk][1], aQl[kk][2], aQl[kk][3],
                             kh[jj * 2], kh[jj * 2 + 1]);
                }
            }
        }

        // Causal mask (block-local query row)
        if (kt >= n_tiles - 2) {
            const int lim = s0 - LL - base;
            #pragma unroll
            for (int j = 0; j < 8; j++)
                #pragma unroll
                for (int t = 0; t < 4; t++) {
                    const int col = j * 8 + qn * 2 + (t & 1);
                    const int row = wid * 16 + l4 + ((t >> 1) << 3);
                    if (col + lim > row) Sc[j][t] = -1e30f;
                }
        }

        // Online softmax (per row-half; 4-lane shfl reductions)
        #pragma unroll
        for (int h = 0; h < 2; h++) {
            float mt = -1e30f;
            #pragma unroll
            for (int j = 0; j < 8; j++)
                mt = fmaxf(mt, fmaxf(Sc[j][2 * h], Sc[j][2 * h + 1]));
            mt = fmaxf(mt, __shfl_xor_sync(0xffffffffu, mt, 1));
            mt = fmaxf(mt, __shfl_xor_sync(0xffffffffu, mt, 2));
            const float mn = fmaxf(mrow[h], mt);
            const float alpha = ex2(mrow[h] - mn);
            mrow[h] = mn;
            float ls = 0.f;
            #pragma unroll
            for (int j = 0; j < 8; j++) {
                float p0 = ex2(Sc[j][2 * h] - mn);
                float p1 = ex2(Sc[j][2 * h + 1] - mn);
                Sc[j][2 * h] = p0; Sc[j][2 * h + 1] = p1;
                ls += p0 + p1;
            }
            ls += __shfl_xor_sync(0xffffffffu, ls, 1);
            ls += __shfl_xor_sync(0xffffffffu, ls, 2);
            lrow[h] = lrow[h] * alpha + ls;
            #pragma unroll
            for (int j = 0; j < 8; j++) {
                O[j][2 * h] *= alpha; O[j][2 * h + 1] *= alpha;
            }
        }

        // Pack P -> A fragments (register-only; layouts match)
        uint32_t aPh[4][4], aPl[4][4];
        #pragma unroll
        for (int kk = 0; kk < 4; kk++) {
            const int j0 = 2 * kk, j1 = 2 * kk + 1;
            float l0, l1;
            aPh[kk][0] = pack_hi(Sc[j0][0], Sc[j0][1], l0, l1);
            aPl[kk][0] = pack_bf(l0, l1);
            aPh[kk][1] = pack_hi(Sc[j0][2], Sc[j0][3], l0, l1);
            aPl[kk][1] = pack_bf(l0, l1);
            aPh[kk][2] = pack_hi(Sc[j1][0], Sc[j1][1], l0, l1);
            aPl[kk][2] = pack_bf(l0, l1);
            aPh[kk][3] = pack_hi(Sc[j1][2], Sc[j1][3], l0, l1);
            aPl[kk][3] = pack_bf(l0, l1);
        }

        // O += P V (bf16x3; V^T as B)
        #pragma unroll
        for (int kk = 0; kk < 4; kk++) {
            #pragma unroll
            for (int jp = 0; jp < 4; jp++) {
                const uint32_t off = (uint32_t)(((jp * 2 + (sel >> 1)) * 8 + r8) * APITCH
                                                + kk * 16 + (sel & 1) * 8) * 2;
                uint32_t vh[4], vl[4];
                ldm_x4(vh[0], vh[1], vh[2], vh[3], pVh + off);
                ldm_x4(vl[0], vl[1], vl[2], vl[3], pVl + off);
                #pragma unroll
                for (int jj = 0; jj < 2; jj++) {
                    const int j = jp * 2 + jj;
                    mma16816(O[j], aPh[kk][0], aPh[kk][1], aPh[kk][2], aPh[kk][3],
                             vh[jj * 2], vh[jj * 2 + 1]);
                    mma16816(O[j], aPh[kk][0], aPh[kk][1], aPh[kk][2], aPh[kk][3],
                             vl[jj * 2], vl[jj * 2 + 1]);
                    mma16816(O[j], aPl[kk][0], aPl[kk][1], aPl[kk][2], aPl[kk][3],
                             vh[jj * 2], vh[jj * 2 + 1]);
                }
            }
        }

        __syncthreads();
        if (kt + 2 < n_tiles) prefetch(kt + 2, buf);
    }

    // Epilogue: y = O / l -> bf16-split proj input
    const int b = bh >> 4, hh = bh & 15;
    #pragma unroll
    for (int h = 0; h < 2; h++) {
        const int t = base + wid * 16 + l4 + h * 8;
        const float inv = 1.f / lrow[h];
        #pragma unroll
        for (int j = 0; j < 8; j++) {
            const float y0 = O[j][2 * h] * inv;
            const float y1 = O[j][2 * h + 1] * inv;
            float l0, l1;
            uint32_t hi = pack_hi(y0, y1, l0, l1);
            uint32_t lo = pack_bf(l0, l1);
            const size_t off = ((size_t)(b * TT + t)) * CC + hh * 64 + j * 8 + qn * 2;
            *(uint32_t*)(g_yhi + off) = hi;
            *(uint32_t*)(g_ylo + off) = lo;
        }
    }
}

// ---------------------------------------------------------------------------
// Fused prep kernel: one launch covers x-split, both weight transposes,
// and both KV-cache conversions. All regions use 256-thread blocks.
// ---------------------------------------------------------------------------
#define NB_XS 4096
#define NB_WQ 3072
#define NB_WP 1024
#define NB_KC 16384
#define NB_VC 16384
#define NB_TOTAL (NB_XS + NB_WQ + NB_WP + NB_KC + NB_VC)

__global__ __launch_bounds__(256) void prep_fused(
    const float* __restrict__ x,
    const float* __restrict__ kc,
    const float* __restrict__ vc,
    const float* __restrict__ Wqkv,
    const float* __restrict__ Wproj)
{
    __shared__ float tile[32][33];
    const int bid = blockIdx.x;
    const int tid = threadIdx.x;

    if (bid < NB_XS) {
        // ---- x split ----
        const int i = bid * 256 + tid;            // float4 index < 1048576
        float4 v = ((const float4*)x)[i];
        __nv_bfloat16 hh[4], ll[4];
        float a[4] = {v.x, v.y, v.z, v.w};
        #pragma unroll
        for (int j = 0; j < 4; j++) {
            hh[j] = __float2bfloat16_rn(a[j]);
            ll[j] = __float2bfloat16_rn(a[j] - __bfloat162float(hh[j]));
        }
        ((uint2*)g_xhi)[i] = *(uint2*)hh;
        ((uint2*)g_xlo)[i] = *(uint2*)ll;
    } else if (bid < NB_XS + NB_WQ + NB_WP) {
        // ---- weight transpose-split ----
        const float* W;
        __nv_bfloat16 *hi, *lo;
        int f, N;
        if (bid < NB_XS + NB_WQ) {
            f = bid - NB_XS; W = Wqkv; hi = g_wqkv_hi; lo = g_wqkv_lo; N = 3072;
        } else {
            f = bid - NB_XS - NB_WQ; W = Wproj; hi = g_wp_hi; lo = g_wp_lo; N = 1024;
        }
        const int ntx = N / 32;
        const int nx = (f % ntx) * 32, kx = (f / ntx) * 32;
        const int tx = tid & 31, ty = tid >> 5;
        #pragma unroll
        for (int r = ty; r < 32; r += 8)
            tile[r][tx] = W[(size_t)(kx + r) * N + nx + tx];
        __syncthreads();
        #pragma unroll
        for (int r = ty; r < 32; r += 8) {
            float xx = tile[tx][r];               // = W[kx+tx][nx+r]
            __nv_bfloat16 h = __float2bfloat16_rn(xx);
            __nv_bfloat16 l = __float2bfloat16_rn(xx - __bfloat162float(h));
            size_t o = (size_t)(nx + r) * 1024 + kx + tx;
            hi[o] = h;
            lo[o] = l;
        }
    } else if (bid < NB_XS + NB_WQ + NB_WP + NB_KC) {
        // ---- K cache convert ----
        const size_t i = (size_t)(bid - NB_XS - NB_WQ - NB_WP) * 256 + tid;
        float4 v = ((const float4*)kc)[i];
        const size_t flat = i * 4;
        const size_t bh = flat >> 17;
        const size_t rem = flat & 131071;
        const size_t s = rem >> 6, e = rem & 63;
        __nv_bfloat16 hh[4], ll[4];
        float a[4] = {v.x, v.y, v.z, v.w};
        #pragma unroll
        for (int j = 0; j < 4; j++) {
            hh[j] = __float2bfloat16_rn(a[j]);
            ll[j] = __float2bfloat16_rn(a[j] - __bfloat162float(hh[j]));
        }
        const size_t off = (bh * SQ + s) * 64 + e;
        *(uint2*)(g_khi + off) = *(uint2*)hh;
        *(uint2*)(g_klo + off) = *(uint2*)ll;
    } else {
        // ---- V cache transpose-convert ----
        const int f = bid - NB_XS - NB_WQ - NB_WP - NB_KC;   // [0, 16384)
        const int sx = f & 63;           // s-tile
        const int ey = (f >> 6) & 1;     // e-tile
        const int bh = f >> 7;           // [0,128)
        const int s0 = sx * 32, e0 = ey * 32;
        const int tx = tid & 31, ty = tid >> 5;
        #pragma unroll
        for (int r = ty; r < 32; r += 8)
            tile[r][tx] = vc[((size_t)bh * LL + s0 + r) * 64 + e0 + tx];
        __syncthreads();
        #pragma unroll
        for (int r = ty; r < 32; r += 8) {
            float xx = tile[tx][r];   // = vc[bh][s0+tx][e0+r]
            __nv_bfloat16 h = __float2bfloat16_rn(xx);
            __nv_bfloat16 l = __float2bfloat16_rn(xx - __bfloat162float(h));
            const size_t off = ((size_t)bh * 64 + e0 + r) * SQ + s0 + tx;
            g_vthi[off] = h;
            g_vtlo[off] = l;
        }
    }
}

// ---------------------------------------------------------------------------
extern "C" void kernel_launch(void* const* d_in, const int* in_sizes, int n_in,
                              void* d_out, int out_size) {
    const float* x       = (const float*)d_in[0];
    const float* k_cache = (const float*)d_in[1];
    const float* v_cache = (const float*)d_in[2];
    const float* Wqkv    = (const float*)d_in[3];
    const float* bqkv    = (const float*)d_in[4];
    const float* Wproj   = (const float*)d_in[5];
    const float* bproj   = (const float*)d_in[6];
    float* out           = (float*)d_out;

    cudaFuncSetAttribute(qkv_mma_kernel, cudaFuncAttributeMaxDynamicSharedMemorySize,
                         GEMM_DYN_BYTES);
    cudaFuncSetAttribute(proj_mma_kernel, cudaFuncAttributeMaxDynamicSharedMemorySize,
                         GEMM_DYN_BYTES);
    cudaFuncSetAttribute(attn_mma_kernel, cudaFuncAttributeMaxDynamicSharedMemorySize,
                         ATT_DYN_BYTES);

    prep_fused<<<NB_TOTAL, 256>>>(x, k_cache, v_cache, Wqkv, Wproj);

    qkv_mma_kernel<<<dim3(24, 32), 256, GEMM_DYN_BYTES>>>(bqkv);
    attn_mma_kernel<<<dim3(4, 128), 256, ATT_DYN_BYTES>>>();
    proj_mma_kernel<<<dim3(8, 32), 256, GEMM_DYN_BYTES>>>(bproj, out);
}

// round 11
// speedup vs baseline: 1.5353x; 1.0596x over previous
#include <cuda_runtime.h>
#include <cuda_bf16.h>
#include <cstdint>
#include <math.h>

#define BB 8
#define TT 512
#define CC 1024
#define HH 16
#define EE 64
#define LL 2048
#define SQ 2560                     // L + T
#define QSCALE 0.1803368801111244f  // 0.125 * log2(e)

// ---------------------------------------------------------------------------
// Scratch (__device__ globals; no allocation allowed)
// ---------------------------------------------------------------------------
__device__ __nv_bfloat16 g_xhi[BB*TT*CC];
__device__ __nv_bfloat16 g_xlo[BB*TT*CC];
__device__ __nv_bfloat16 g_yhi[BB*TT*CC];
__device__ __nv_bfloat16 g_ylo[BB*TT*CC];
__device__ __nv_bfloat16 g_wqkv_hi[3*CC*CC];   // [N=3072][K=1024]
__device__ __nv_bfloat16 g_wqkv_lo[3*CC*CC];
__device__ __nv_bfloat16 g_wp_hi[CC*CC];       // [N=1024][K=1024]
__device__ __nv_bfloat16 g_wp_lo[CC*CC];

__device__ __nv_bfloat16 g_qhi[BB*HH*TT*EE];   // [bh][t][e], pre-scaled
__device__ __nv_bfloat16 g_qlo[BB*HH*TT*EE];
__device__ __nv_bfloat16 g_khi[BB*HH*SQ*EE];   // [bh][s][e]
__device__ __nv_bfloat16 g_klo[BB*HH*SQ*EE];
__device__ __nv_bfloat16 g_vthi[BB*HH*EE*SQ];  // [bh][e][s] (transposed)
__device__ __nv_bfloat16 g_vtlo[BB*HH*EE*SQ];

// ---------------------------------------------------------------------------
// Helpers
// ---------------------------------------------------------------------------
__device__ __forceinline__ void mma16816(float c[4],
    uint32_t a0, uint32_t a1, uint32_t a2, uint32_t a3,
    uint32_t b0, uint32_t b1)
{
    asm volatile(
        "mma.sync.aligned.m16n8k16.row.col.f32.bf16.bf16.f32 "
        "{%0,%1,%2,%3}, {%4,%5,%6,%7}, {%8,%9}, {%0,%1,%2,%3};"
        : "+f"(c[0]), "+f"(c[1]), "+f"(c[2]), "+f"(c[3])
        : "r"(a0), "r"(a1), "r"(a2), "r"(a3), "r"(b0), "r"(b1));
}
__device__ __forceinline__ void ldm_x4(uint32_t& r0, uint32_t& r1,
                                       uint32_t& r2, uint32_t& r3, uint32_t addr)
{
    asm volatile("ldmatrix.sync.aligned.m8n8.x4.shared.b16 {%0,%1,%2,%3}, [%4];"
        : "=r"(r0), "=r"(r1), "=r"(r2), "=r"(r3) : "r"(addr));
}
__device__ __forceinline__ void cpasync16(uint32_t dst, const void* src) {
    asm volatile("cp.async.cg.shared.global [%0], [%1], 16;"
        :: "r"(dst), "l"(src) : "memory");
}
#define CP_COMMIT() asm volatile("cp.async.commit_group;" ::: "memory")
#define CP_WAIT1()  asm volatile("cp.async.wait_group 1;" ::: "memory")
#define CP_WAIT0()  asm volatile("cp.async.wait_group 0;" ::: "memory")

__device__ __forceinline__ float ex2(float x) {
    float r; asm("ex2.approx.ftz.f32 %0, %1;" : "=f"(r) : "f"(x)); return r;
}
__device__ __forceinline__ uint32_t pack_hi(float a, float b, float& ra, float& rb) {
    __nv_bfloat162 h = __floats2bfloat162_rn(a, b);
    ra = a - __low2float(h); rb = b - __high2float(h);
    return *(uint32_t*)&h;
}
__device__ __forceinline__ uint32_t pack_bf(float a, float b) {
    __nv_bfloat162 h = __floats2bfloat162_rn(a, b);
    return *(uint32_t*)&h;
}

// ---------------------------------------------------------------------------
// bf16x3 mma.sync GEMM core (772us configuration, unchanged):
// PITCH 40, K-chunk 32, double-buffered cp.async, two syncs per chunk.
// ---------------------------------------------------------------------------
#define PITCH 40
#define PLANE (128 * PITCH)            // halfwords per plane
#define GSTAGE (4 * PLANE)             // halfwords per stage
#define GEMM_DYN_BYTES (2 * GSTAGE * 2)   // 81920

extern __shared__ __nv_bfloat16 dyn_smem[];

__device__ __forceinline__ void tc_gemm_mma(
    const __nv_bfloat16* __restrict__ Ahi, const __nv_bfloat16* __restrict__ Alo,
    const __nv_bfloat16* __restrict__ Bhi, const __nv_bfloat16* __restrict__ Blo,
    int m0, int n0, float c[4][4][4])
{
    const int tid = threadIdx.x;
    const int wid = tid >> 5, lane = tid & 31;
    const int wm = wid & 1, wn = wid >> 1;
    const int sel = lane >> 3, r8 = lane & 7;

    #pragma unroll
    for (int i = 0; i < 4; i++)
        #pragma unroll
        for (int j = 0; j < 4; j++)
            #pragma unroll
            for (int t = 0; t < 4; t++) c[i][j][t] = 0.f;

    const uint32_t sbase = (uint32_t)__cvta_generic_to_shared(dyn_smem);
    const __nv_bfloat16* planes[4] = {Ahi, Alo, Bhi, Blo};

    auto prefetch = [&](int kc, int buf) {
        const int k0 = kc * 32;
        #pragma unroll
        for (int p = 0; p < 4; p++) {
            const __nv_bfloat16* src = planes[p];
            const int br = (p < 2) ? m0 : n0;
            const uint32_t dplane = sbase + (uint32_t)(buf * GSTAGE + p * PLANE) * 2;
            #pragma unroll
            for (int i = 0; i < 2; i++) {
                const int idx = i * 256 + tid;        // [0,512)
                const int row = idx >> 2, seg = idx & 3;
                cpasync16(dplane + (uint32_t)(row * PITCH + seg * 8) * 2,
                          src + (size_t)(br + row) * 1024 + k0 + seg * 8);
            }
        }
        CP_COMMIT();
    };

    prefetch(0, 0);
    prefetch(1, 1);

    for (int kc = 0; kc < 32; kc++) {
        const int buf = kc & 1;
        if (kc == 31) { CP_WAIT0(); } else { CP_WAIT1(); }
        __syncthreads();

        const uint32_t ab  = sbase + (uint32_t)(buf * GSTAGE) * 2;
        const uint32_t pAh = ab;
        const uint32_t pAl = ab + (uint32_t)PLANE * 2;
        const uint32_t pBh = ab + (uint32_t)(2 * PLANE) * 2;
        const uint32_t pBl = ab + (uint32_t)(3 * PLANE) * 2;

        #pragma unroll
        for (int k16 = 0; k16 < 2; k16++) {
            const int kb = k16 * 16;
            uint32_t aH[4][4], aL[4][4], bH[2][4], bL[2][4];
            #pragma unroll
            for (int i = 0; i < 4; i++) {
                const uint32_t off = (uint32_t)((wm * 64 + i * 16 + r8 + (sel & 1) * 8) * PITCH
                                                + kb + (sel >> 1) * 8) * 2;
                ldm_x4(aH[i][0], aH[i][1], aH[i][2], aH[i][3], pAh + off);
                ldm_x4(aL[i][0], aL[i][1], aL[i][2], aL[i][3], pAl + off);
            }
            #pragma unroll
            for (int jp = 0; jp < 2; jp++) {
                const uint32_t off = (uint32_t)(((wn * 32 + (jp * 2 + (sel >> 1)) * 8) + r8) * PITCH
                                                + kb + (sel & 1) * 8) * 2;
                ldm_x4(bH[jp][0], bH[jp][1], bH[jp][2], bH[jp][3], pBh + off);
                ldm_x4(bL[jp][0], bL[jp][1], bL[jp][2], bL[jp][3], pBl + off);
            }
            #pragma unroll
            for (int i = 0; i < 4; i++)
                #pragma unroll
                for (int j = 0; j < 4; j++) {
                    const uint32_t b0h = bH[j >> 1][(j & 1) * 2];
                    const uint32_t b1h = bH[j >> 1][(j & 1) * 2 + 1];
                    const uint32_t b0l = bL[j >> 1][(j & 1) * 2];
                    const uint32_t b1l = bL[j >> 1][(j & 1) * 2 + 1];
                    mma16816(c[i][j], aH[i][0], aH[i][1], aH[i][2], aH[i][3], b0h, b1h);
                    mma16816(c[i][j], aH[i][0], aH[i][1], aH[i][2], aH[i][3], b0l, b1l);
                    mma16816(c[i][j], aL[i][0], aL[i][1], aL[i][2], aL[i][3], b0h, b1h);
                }
        }
        __syncthreads();
        if (kc + 2 < 32) prefetch(kc + 2, buf);
    }
}

// ---------------------------------------------------------------------------
// QKV GEMM: epilogue writes pre-scaled bf16-split q, k (seq offset 2048),
// v transposed — exactly the layouts the attention kernel consumes.
// ---------------------------------------------------------------------------
__global__ __launch_bounds__(256) void qkv_mma_kernel(const float* __restrict__ bias)
{
    const int m0 = blockIdx.y * 128, n0 = blockIdx.x * 128;
    float c[4][4][4];
    tc_gemm_mma(g_xhi, g_xlo, g_wqkv_hi, g_wqkv_lo, m0, n0, c);

    const int tid = threadIdx.x, wid = tid >> 5, lane = tid & 31;
    const int wm = wid & 1, wn = wid >> 1;
    const int qr = lane >> 2, qc = lane & 3;

    #pragma unroll
    for (int i = 0; i < 4; i++) {
        #pragma unroll
        for (int j = 0; j < 4; j++) {
            const int n = n0 + wn * 32 + j * 8 + qc * 2;
            const int part = n >> 10;
            const int h = (n & 1023) >> 6;
            const int e = n & 63;
            const float b0 = bias[n], b1 = bias[n + 1];
            #pragma unroll
            for (int half = 0; half < 2; half++) {
                const int m = m0 + wm * 64 + i * 16 + qr + half * 8;
                const int bb = m >> 9, t = m & 511;
                const int bh = bb * HH + h;
                float v0 = c[i][j][half * 2] + b0;
                float v1 = c[i][j][half * 2 + 1] + b1;
                if (part == 0) {
                    v0 *= QSCALE; v1 *= QSCALE;
                    float l0, l1;
                    uint32_t hi = pack_hi(v0, v1, l0, l1);
                    uint32_t lo = pack_bf(l0, l1);
                    size_t off = ((size_t)bh * TT + t) * 64 + e;
                    *(uint32_t*)(g_qhi + off) = hi;
                    *(uint32_t*)(g_qlo + off) = lo;
                } else if (part == 1) {
                    float l0, l1;
                    uint32_t hi = pack_hi(v0, v1, l0, l1);
                    uint32_t lo = pack_bf(l0, l1);
                    size_t off = ((size_t)bh * SQ + LL + t) * 64 + e;
                    *(uint32_t*)(g_khi + off) = hi;
                    *(uint32_t*)(g_klo + off) = lo;
                } else {
                    __nv_bfloat16 h0 = __float2bfloat16_rn(v0);
                    __nv_bfloat16 h1 = __float2bfloat16_rn(v1);
                    __nv_bfloat16 l0 = __float2bfloat16_rn(v0 - __bfloat162float(h0));
                    __nv_bfloat16 l1 = __float2bfloat16_rn(v1 - __bfloat162float(h1));
                    size_t o0 = ((size_t)bh * 64 + e) * SQ + LL + t;
                    size_t o1 = ((size_t)bh * 64 + e + 1) * SQ + LL + t;
                    g_vthi[o0] = h0; g_vtlo[o0] = l0;
                    g_vthi[o1] = h1; g_vtlo[o1] = l1;
                }
            }
        }
    }
}

// ---------------------------------------------------------------------------
// Proj GEMM
// ---------------------------------------------------------------------------
__global__ __launch_bounds__(256) void proj_mma_kernel(const float* __restrict__ bias,
                                                       float* __restrict__ out)
{
    const int m0 = blockIdx.y * 128, n0 = blockIdx.x * 128;
    float c[4][4][4];
    tc_gemm_mma(g_yhi, g_ylo, g_wp_hi, g_wp_lo, m0, n0, c);

    const int tid = threadIdx.x, wid = tid >> 5, lane = tid & 31;
    const int wm = wid & 1, wn = wid >> 1;
    const int qr = lane >> 2, qc = lane & 3;

    #pragma unroll
    for (int i = 0; i < 4; i++) {
        #pragma unroll
        for (int j = 0; j < 4; j++) {
            const int n = n0 + wn * 32 + j * 8 + qc * 2;
            const float b0 = bias[n], b1 = bias[n + 1];
            #pragma unroll
            for (int half = 0; half < 2; half++) {
                const int m = m0 + wm * 64 + i * 16 + qr + half * 8;
                float2 w = make_float2(c[i][j][half * 2] + b0,
                                       c[i][j][half * 2 + 1] + b1);
                *(float2*)&out[(size_t)m * 1024 + n] = w;
            }
        }
    }
}

// ---------------------------------------------------------------------------
// Flash attention: 64 queries/CTA, 128 threads (4 warps x 16 rows), 3 CTA/SM.
// Same per-thread fragment structure as the 772us body; only the CTA shape
// and grid change. Double-buffered K/V, two __syncthreads per tile.
// Only the FINAL tile intersects the causal diagonal (64-query granularity).
// ---------------------------------------------------------------------------
#define APITCH 72
#define APLANE (64 * APITCH)           // halfwords per array
#define ASTAGE (4 * APLANE)            // Kh,Kl,Vh,Vl
#define ATT_DYN_BYTES (2 * ASTAGE * 2) // 73728

__global__ __launch_bounds__(128, 3) void attn_mma_kernel()
{
    const int tid = threadIdx.x, wid = tid >> 5, lane = tid & 31;
    const int l4 = lane >> 2, qn = lane & 3;
    const int sel = lane >> 3, r8 = lane & 7;
    const int bh = blockIdx.y;
    const int qb = 7 - blockIdx.x;      // heavy blocks first
    const int base = qb * 64;

    const uint32_t sbase = (uint32_t)__cvta_generic_to_shared(dyn_smem);

    // Persistent Q fragments (pre-scaled bf16 hi/lo)
    uint32_t aQh[4][4], aQl[4][4];
    {
        const __nv_bfloat16* qh = g_qhi + ((size_t)bh * TT + base + wid * 16) * 64;
        const __nv_bfloat16* ql = g_qlo + ((size_t)bh * TT + base + wid * 16) * 64;
        #pragma unroll
        for (int kk = 0; kk < 4; kk++) {
            const int c0 = kk * 16 + qn * 2;
            aQh[kk][0] = *(const uint32_t*)(qh + l4 * 64 + c0);
            aQh[kk][1] = *(const uint32_t*)(qh + (l4 + 8) * 64 + c0);
            aQh[kk][2] = *(const uint32_t*)(qh + l4 * 64 + c0 + 8);
            aQh[kk][3] = *(const uint32_t*)(qh + (l4 + 8) * 64 + c0 + 8);
            aQl[kk][0] = *(const uint32_t*)(ql + l4 * 64 + c0);
            aQl[kk][1] = *(const uint32_t*)(ql + (l4 + 8) * 64 + c0);
            aQl[kk][2] = *(const uint32_t*)(ql + l4 * 64 + c0 + 8);
            aQl[kk][3] = *(const uint32_t*)(ql + (l4 + 8) * 64 + c0 + 8);
        }
    }

    float O[8][4];
    #pragma unroll
    for (int j = 0; j < 8; j++)
        #pragma unroll
        for (int t = 0; t < 4; t++) O[j][t] = 0.f;
    float mrow[2] = {-1e30f, -1e30f};
    float lrow[2] = {0.f, 0.f};

    const __nv_bfloat16* Kh  = g_khi  + (size_t)bh * SQ * 64;
    const __nv_bfloat16* Kl  = g_klo  + (size_t)bh * SQ * 64;
    const __nv_bfloat16* Vth = g_vthi + (size_t)bh * 64 * SQ;
    const __nv_bfloat16* Vtl = g_vtlo + (size_t)bh * 64 * SQ;

    const int n_tiles = 32 + qb + 1;

    auto prefetch = [&](int kt, int buf) {
        const int s0 = kt * 64;
        const uint32_t dst = sbase + (uint32_t)(buf * ASTAGE) * 2;
        #pragma unroll
        for (int i = 0; i < 4; i++) {
            const int idx = i * 128 + tid;        // [0,512)
            const int row = idx >> 3, seg = idx & 7;
            const uint32_t doff = (uint32_t)(row * APITCH + seg * 8) * 2;
            cpasync16(dst + doff,
                      Kh + (size_t)(s0 + row) * 64 + seg * 8);
            cpasync16(dst + (uint32_t)APLANE * 2 + doff,
                      Kl + (size_t)(s0 + row) * 64 + seg * 8);
            cpasync16(dst + (uint32_t)(2 * APLANE) * 2 + doff,
                      Vth + (size_t)row * SQ + s0 + seg * 8);
            cpasync16(dst + (uint32_t)(3 * APLANE) * 2 + doff,
                      Vtl + (size_t)row * SQ + s0 + seg * 8);
        }
        CP_COMMIT();
    };

    prefetch(0, 0);
    if (n_tiles > 1) prefetch(1, 1);

    for (int kt = 0; kt < n_tiles; kt++) {
        const int buf = kt & 1;
        if (kt >= n_tiles - 1) { CP_WAIT0(); } else { CP_WAIT1(); }
        __syncthreads();

        const uint32_t ab  = sbase + (uint32_t)(buf * ASTAGE) * 2;
        const uint32_t pKh = ab;
        const uint32_t pKl = ab + (uint32_t)APLANE * 2;
        const uint32_t pVh = ab + (uint32_t)(2 * APLANE) * 2;
        const uint32_t pVl = ab + (uint32_t)(3 * APLANE) * 2;

        // S = Q K^T (bf16x3)
        float Sc[8][4];
        #pragma unroll
        for (int j = 0; j < 8; j++)
            #pragma unroll
            for (int t = 0; t < 4; t++) Sc[j][t] = 0.f;

        #pragma unroll
        for (int kk = 0; kk < 4; kk++) {
            #pragma unroll
            for (int jp = 0; jp < 4; jp++) {
                const uint32_t off = (uint32_t)(((jp * 2 + (sel >> 1)) * 8 + r8) * APITCH
                                                + kk * 16 + (sel & 1) * 8) * 2;
                uint32_t kh[4], kl[4];
                ldm_x4(kh[0], kh[1], kh[2], kh[3], pKh + off);
                ldm_x4(kl[0], kl[1], kl[2], kl[3], pKl + off);
                #pragma unroll
                for (int jj = 0; jj < 2; jj++) {
                    const int j = jp * 2 + jj;
                    mma16816(Sc[j], aQh[kk][0], aQh[kk][1], aQh[kk][2], aQh[kk][3],
                             kh[jj * 2], kh[jj * 2 + 1]);
                    mma16816(Sc[j], aQh[kk][0], aQh[kk][1], aQh[kk][2], aQh[kk][3],
                             kl[jj * 2], kl[jj * 2 + 1]);
                    mma16816(Sc[j], aQl[kk][0], aQl[kk][1], aQl[kk][2], aQl[kk][3],
                             kh[jj * 2], kh[jj * 2 + 1]);
                }
            }
        }

        // Causal mask — only the final tile intersects the diagonal
        if (kt == n_tiles - 1) {
            #pragma unroll
            for (int j = 0; j < 8; j++)
                #pragma unroll
                for (int t = 0; t < 4; t++) {
                    const int col = j * 8 + qn * 2 + (t & 1);
                    const int row = wid * 16 + l4 + ((t >> 1) << 3);
                    if (col > row) Sc[j][t] = -1e30f;
                }
        }

        // Online softmax (per row-half; 4-lane shfl reductions)
        #pragma unroll
        for (int h = 0; h < 2; h++) {
            float mt = -1e30f;
            #pragma unroll
            for (int j = 0; j < 8; j++)
                mt = fmaxf(mt, fmaxf(Sc[j][2 * h], Sc[j][2 * h + 1]));
            mt = fmaxf(mt, __shfl_xor_sync(0xffffffffu, mt, 1));
            mt = fmaxf(mt, __shfl_xor_sync(0xffffffffu, mt, 2));
            const float mn = fmaxf(mrow[h], mt);
            const float alpha = ex2(mrow[h] - mn);
            mrow[h] = mn;
            float ls = 0.f;
            #pragma unroll
            for (int j = 0; j < 8; j++) {
                float p0 = ex2(Sc[j][2 * h] - mn);
                float p1 = ex2(Sc[j][2 * h + 1] - mn);
                Sc[j][2 * h] = p0; Sc[j][2 * h + 1] = p1;
                ls += p0 + p1;
            }
            ls += __shfl_xor_sync(0xffffffffu, ls, 1);
            ls += __shfl_xor_sync(0xffffffffu, ls, 2);
            lrow[h] = lrow[h] * alpha + ls;
            #pragma unroll
            for (int j = 0; j < 8; j++) {
                O[j][2 * h] *= alpha; O[j][2 * h + 1] *= alpha;
            }
        }

        // Pack P -> A fragments (register-only; layouts match)
        uint32_t aPh[4][4], aPl[4][4];
        #pragma unroll
        for (int kk = 0; kk < 4; kk++) {
            const int j0 = 2 * kk, j1 = 2 * kk + 1;
            float l0, l1;
            aPh[kk][0] = pack_hi(Sc[j0][0], Sc[j0][1], l0, l1);
            aPl[kk][0] = pack_bf(l0, l1);
            aPh[kk][1] = pack_hi(Sc[j0][2], Sc[j0][3], l0, l1);
            aPl[kk][1] = pack_bf(l0, l1);
            aPh[kk][2] = pack_hi(Sc[j1][0], Sc[j1][1], l0, l1);
            aPl[kk][2] = pack_bf(l0, l1);
            aPh[kk][3] = pack_hi(Sc[j1][2], Sc[j1][3], l0, l1);
            aPl[kk][3] = pack_bf(l0, l1);
        }

        // O += P V (bf16x3; V^T as B)
        #pragma unroll
        for (int kk = 0; kk < 4; kk++) {
            #pragma unroll
            for (int jp = 0; jp < 4; jp++) {
                const uint32_t off = (uint32_t)(((jp * 2 + (sel >> 1)) * 8 + r8) * APITCH
                                                + kk * 16 + (sel & 1) * 8) * 2;
                uint32_t vh[4], vl[4];
                ldm_x4(vh[0], vh[1], vh[2], vh[3], pVh + off);
                ldm_x4(vl[0], vl[1], vl[2], vl[3], pVl + off);
                #pragma unroll
                for (int jj = 0; jj < 2; jj++) {
                    const int j = jp * 2 + jj;
                    mma16816(O[j], aPh[kk][0], aPh[kk][1], aPh[kk][2], aPh[kk][3],
                             vh[jj * 2], vh[jj * 2 + 1]);
                    mma16816(O[j], aPh[kk][0], aPh[kk][1], aPh[kk][2], aPh[kk][3],
                             vl[jj * 2], vl[jj * 2 + 1]);
                    mma16816(O[j], aPl[kk][0], aPl[kk][1], aPl[kk][2], aPl[kk][3],
                             vh[jj * 2], vh[jj * 2 + 1]);
                }
            }
        }

        __syncthreads();
        if (kt + 2 < n_tiles) prefetch(kt + 2, buf);
    }

    // Epilogue: y = O / l -> bf16-split proj input
    const int b = bh >> 4, hh = bh & 15;
    #pragma unroll
    for (int h = 0; h < 2; h++) {
        const int t = base + wid * 16 + l4 + h * 8;
        const float inv = 1.f / lrow[h];
        #pragma unroll
        for (int j = 0; j < 8; j++) {
            const float y0 = O[j][2 * h] * inv;
            const float y1 = O[j][2 * h + 1] * inv;
            float l0, l1;
            uint32_t hi = pack_hi(y0, y1, l0, l1);
            uint32_t lo = pack_bf(l0, l1);
            const size_t off = ((size_t)(b * TT + t)) * CC + hh * 64 + j * 8 + qn * 2;
            *(uint32_t*)(g_yhi + off) = hi;
            *(uint32_t*)(g_ylo + off) = lo;
        }
    }
}

// ---------------------------------------------------------------------------
// Fused prep kernel (unchanged from 772us version)
// ---------------------------------------------------------------------------
#define NB_XS 4096
#define NB_WQ 3072
#define NB_WP 1024
#define NB_KC 16384
#define NB_VC 16384
#define NB_TOTAL (NB_XS + NB_WQ + NB_WP + NB_KC + NB_VC)

__global__ __launch_bounds__(256) void prep_fused(
    const float* __restrict__ x,
    const float* __restrict__ kc,
    const float* __restrict__ vc,
    const float* __restrict__ Wqkv,
    const float* __restrict__ Wproj)
{
    __shared__ float tile[32][33];
    const int bid = blockIdx.x;
    const int tid = threadIdx.x;

    if (bid < NB_XS) {
        const int i = bid * 256 + tid;
        float4 v = ((const float4*)x)[i];
        __nv_bfloat16 hh[4], ll[4];
        float a[4] = {v.x, v.y, v.z, v.w};
        #pragma unroll
        for (int j = 0; j < 4; j++) {
            hh[j] = __float2bfloat16_rn(a[j]);
            ll[j] = __float2bfloat16_rn(a[j] - __bfloat162float(hh[j]));
        }
        ((uint2*)g_xhi)[i] = *(uint2*)hh;
        ((uint2*)g_xlo)[i] = *(uint2*)ll;
    } else if (bid < NB_XS + NB_WQ + NB_WP) {
        const float* W;
        __nv_bfloat16 *hi, *lo;
        int f, N;
        if (bid < NB_XS + NB_WQ) {
            f = bid - NB_XS; W = Wqkv; hi = g_wqkv_hi; lo = g_wqkv_lo; N = 3072;
        } else {
            f = bid - NB_XS - NB_WQ; W = Wproj; hi = g_wp_hi; lo = g_wp_lo; N = 1024;
        }
        const int ntx = N / 32;
        const int nx = (f % ntx) * 32, kx = (f / ntx) * 32;
        const int tx = tid & 31, ty = tid >> 5;
        #pragma unroll
        for (int r = ty; r < 32; r += 8)
            tile[r][tx] = W[(size_t)(kx + r) * N + nx + tx];
        __syncthreads();
        #pragma unroll
        for (int r = ty; r < 32; r += 8) {
            float xx = tile[tx][r];
            __nv_bfloat16 h = __float2bfloat16_rn(xx);
            __nv_bfloat16 l = __float2bfloat16_rn(xx - __bfloat162float(h));
            size_t o = (size_t)(nx + r) * 1024 + kx + tx;
            hi[o] = h;
            lo[o] = l;
        }
    } else if (bid < NB_XS + NB_WQ + NB_WP + NB_KC) {
        const size_t i = (size_t)(bid - NB_XS - NB_WQ - NB_WP) * 256 + tid;
        float4 v = ((const float4*)kc)[i];
        const size_t flat = i * 4;
        const size_t bh = flat >> 17;
        const size_t rem = flat & 131071;
        const size_t s = rem >> 6, e = rem & 63;
        __nv_bfloat16 hh[4], ll[4];
        float a[4] = {v.x, v.y, v.z, v.w};
        #pragma unroll
        for (int j = 0; j < 4; j++) {
            hh[j] = __float2bfloat16_rn(a[j]);
            ll[j] = __float2bfloat16_rn(a[j] - __bfloat162float(hh[j]));
        }
        const size_t off = (bh * SQ + s) * 64 + e;
        *(uint2*)(g_khi + off) = *(uint2*)hh;
        *(uint2*)(g_klo + off) = *(uint2*)ll;
    } else {
        const int f = bid - NB_XS - NB_WQ - NB_WP - NB_KC;
        const int sx = f & 63;
        const int ey = (f >> 6) & 1;
        const int bh = f >> 7;
        const int s0 = sx * 32, e0 = ey * 32;
        const int tx = tid & 31, ty = tid >> 5;
        #pragma unroll
        for (int r = ty; r < 32; r += 8)
            tile[r][tx] = vc[((size_t)bh * LL + s0 + r) * 64 + e0 + tx];
        __syncthreads();
        #pragma unroll
        for (int r = ty; r < 32; r += 8) {
            float xx = tile[tx][r];
            __nv_bfloat16 h = __float2bfloat16_rn(xx);
            __nv_bfloat16 l = __float2bfloat16_rn(xx - __bfloat162float(h));
            const size_t off = ((size_t)bh * 64 + e0 + r) * SQ + s0 + tx;
            g_vthi[off] = h;
            g_vtlo[off] = l;
        }
    }
}

// ---------------------------------------------------------------------------
extern "C" void kernel_launch(void* const* d_in, const int* in_sizes, int n_in,
                              void* d_out, int out_size) {
    const float* x       = (const float*)d_in[0];
    const float* k_cache = (const float*)d_in[1];
    const float* v_cache = (const float*)d_in[2];
    const float* Wqkv    = (const float*)d_in[3];
    const float* bqkv    = (const float*)d_in[4];
    const float* Wproj   = (const float*)d_in[5];
    const float* bproj   = (const float*)d_in[6];
    float* out           = (float*)d_out;

    cudaFuncSetAttribute(qkv_mma_kernel, cudaFuncAttributeMaxDynamicSharedMemorySize,
                         GEMM_DYN_BYTES);
    cudaFuncSetAttribute(proj_mma_kernel, cudaFuncAttributeMaxDynamicSharedMemorySize,
                         GEMM_DYN_BYTES);
    cudaFuncSetAttribute(attn_mma_kernel, cudaFuncAttributeMaxDynamicSharedMemorySize,
                         ATT_DYN_BYTES);

    prep_fused<<<NB_TOTAL, 256>>>(x, k_cache, v_cache, Wqkv, Wproj);

    qkv_mma_kernel<<<dim3(24, 32), 256, GEMM_DYN_BYTES>>>(bqkv);
    attn_mma_kernel<<<dim3(8, 128), 128, ATT_DYN_BYTES>>>();
    proj_mma_kernel<<<dim3(8, 32), 256, GEMM_DYN_BYTES>>>(bproj, out);
}

// round 16
// speedup vs baseline: 1.8331x; 1.1940x over previous
#include <cuda_runtime.h>
#include <cuda_bf16.h>
#include <cuda_fp16.h>
#include <cstdint>
#include <math.h>

#define BB 8
#define TT 512
#define CC 1024
#define HH 16
#define EE 64
#define LL 2048
#define SQ 2560                     // L + T
#define QSCALE 0.1803368801111244f  // 0.125 * log2(e)

// ---------------------------------------------------------------------------
// Scratch (__device__ globals; no allocation allowed)
// ---------------------------------------------------------------------------
__device__ __nv_bfloat16 g_xhi[BB*TT*CC];
__device__ __nv_bfloat16 g_xlo[BB*TT*CC];
__device__ __nv_bfloat16 g_yhi[BB*TT*CC];
__device__ __nv_bfloat16 g_ylo[BB*TT*CC];
__device__ __nv_bfloat16 g_wqkv_hi[3*CC*CC];   // [N=3072][K=1024]
__device__ __nv_bfloat16 g_wqkv_lo[3*CC*CC];
__device__ __nv_bfloat16 g_wp_hi[CC*CC];       // [N=1024][K=1024]
__device__ __nv_bfloat16 g_wp_lo[CC*CC];

// Attention operands in fp16 (11-bit mantissa -> 2-pass schemes)
__device__ __half g_qhi[BB*HH*TT*EE];   // [bh][t][e], pre-scaled, fp16 hi
__device__ __half g_qlo[BB*HH*TT*EE];   // fp16 lo
__device__ __half g_kf [BB*HH*SQ*EE];   // [bh][s][e], SINGLE fp16
__device__ __half g_vthi[BB*HH*EE*SQ];  // [bh][e][s] transposed, fp16 hi
__device__ __half g_vtlo[BB*HH*EE*SQ];  // fp16 lo

// ---------------------------------------------------------------------------
// Helpers
// ---------------------------------------------------------------------------
__device__ __forceinline__ void mma16816(float c[4],
    uint32_t a0, uint32_t a1, uint32_t a2, uint32_t a3,
    uint32_t b0, uint32_t b1)
{
    asm volatile(
        "mma.sync.aligned.m16n8k16.row.col.f32.bf16.bf16.f32 "
        "{%0,%1,%2,%3}, {%4,%5,%6,%7}, {%8,%9}, {%0,%1,%2,%3};"
        : "+f"(c[0]), "+f"(c[1]), "+f"(c[2]), "+f"(c[3])
        : "r"(a0), "r"(a1), "r"(a2), "r"(a3), "r"(b0), "r"(b1));
}
__device__ __forceinline__ void mma16816h(float c[4],
    uint32_t a0, uint32_t a1, uint32_t a2, uint32_t a3,
    uint32_t b0, uint32_t b1)
{
    asm volatile(
        "mma.sync.aligned.m16n8k16.row.col.f32.f16.f16.f32 "
        "{%0,%1,%2,%3}, {%4,%5,%6,%7}, {%8,%9}, {%0,%1,%2,%3};"
        : "+f"(c[0]), "+f"(c[1]), "+f"(c[2]), "+f"(c[3])
        : "r"(a0), "r"(a1), "r"(a2), "r"(a3), "r"(b0), "r"(b1));
}
__device__ __forceinline__ void ldm_x4(uint32_t& r0, uint32_t& r1,
                                       uint32_t& r2, uint32_t& r3, uint32_t addr)
{
    asm volatile("ldmatrix.sync.aligned.m8n8.x4.shared.b16 {%0,%1,%2,%3}, [%4];"
        : "=r"(r0), "=r"(r1), "=r"(r2), "=r"(r3) : "r"(addr));
}
__device__ __forceinline__ void cpasync16(uint32_t dst, const void* src) {
    asm volatile("cp.async.cg.shared.global [%0], [%1], 16;"
        :: "r"(dst), "l"(src) : "memory");
}
#define CP_COMMIT() asm volatile("cp.async.commit_group;" ::: "memory")
#define CP_WAIT1()  asm volatile("cp.async.wait_group 1;" ::: "memory")
#define CP_WAIT0()  asm volatile("cp.async.wait_group 0;" ::: "memory")

__device__ __forceinline__ float ex2(float x) {
    float r; asm("ex2.approx.ftz.f32 %0, %1;" : "=f"(r) : "f"(x)); return r;
}
__device__ __forceinline__ uint32_t pack_hi(float a, float b, float& ra, float& rb) {
    __nv_bfloat162 h = __floats2bfloat162_rn(a, b);
    ra = a - __low2float(h); rb = b - __high2float(h);
    return *(uint32_t*)&h;
}
__device__ __forceinline__ uint32_t pack_bf(float a, float b) {
    __nv_bfloat162 h = __floats2bfloat162_rn(a, b);
    return *(uint32_t*)&h;
}
__device__ __forceinline__ uint32_t packh_hi(float a, float b, float& ra, float& rb) {
    __half2 h = __floats2half2_rn(a, b);
    ra = a - __low2float(h); rb = b - __high2float(h);
    return *(uint32_t*)&h;
}
__device__ __forceinline__ uint32_t packh(float a, float b) {
    __half2 h = __floats2half2_rn(a, b);
    return *(uint32_t*)&h;
}

// ---------------------------------------------------------------------------
// bf16x3 mma.sync GEMM core (728.8us configuration, unchanged)
// ---------------------------------------------------------------------------
#define PITCH 40
#define PLANE (128 * PITCH)
#define GSTAGE (4 * PLANE)
#define GEMM_DYN_BYTES (2 * GSTAGE * 2)   // 81920

extern __shared__ __nv_bfloat16 dyn_smem[];

__device__ __forceinline__ void tc_gemm_mma(
    const __nv_bfloat16* __restrict__ Ahi, const __nv_bfloat16* __restrict__ Alo,
    const __nv_bfloat16* __restrict__ Bhi, const __nv_bfloat16* __restrict__ Blo,
    int m0, int n0, float c[4][4][4])
{
    const int tid = threadIdx.x;
    const int wid = tid >> 5, lane = tid & 31;
    const int wm = wid & 1, wn = wid >> 1;
    const int sel = lane >> 3, r8 = lane & 7;

    #pragma unroll
    for (int i = 0; i < 4; i++)
        #pragma unroll
        for (int j = 0; j < 4; j++)
            #pragma unroll
            for (int t = 0; t < 4; t++) c[i][j][t] = 0.f;

    const uint32_t sbase = (uint32_t)__cvta_generic_to_shared(dyn_smem);
    const __nv_bfloat16* planes[4] = {Ahi, Alo, Bhi, Blo};

    auto prefetch = [&](int kc, int buf) {
        const int k0 = kc * 32;
        #pragma unroll
        for (int p = 0; p < 4; p++) {
            const __nv_bfloat16* src = planes[p];
            const int br = (p < 2) ? m0 : n0;
            const uint32_t dplane = sbase + (uint32_t)(buf * GSTAGE + p * PLANE) * 2;
            #pragma unroll
            for (int i = 0; i < 2; i++) {
                const int idx = i * 256 + tid;
                const int row = idx >> 2, seg = idx & 3;
                cpasync16(dplane + (uint32_t)(row * PITCH + seg * 8) * 2,
                          src + (size_t)(br + row) * 1024 + k0 + seg * 8);
            }
        }
        CP_COMMIT();
    };

    prefetch(0, 0);
    prefetch(1, 1);

    for (int kc = 0; kc < 32; kc++) {
        const int buf = kc & 1;
        if (kc == 31) { CP_WAIT0(); } else { CP_WAIT1(); }
        __syncthreads();

        const uint32_t ab  = sbase + (uint32_t)(buf * GSTAGE) * 2;
        const uint32_t pAh = ab;
        const uint32_t pAl = ab + (uint32_t)PLANE * 2;
        const uint32_t pBh = ab + (uint32_t)(2 * PLANE) * 2;
        const uint32_t pBl = ab + (uint32_t)(3 * PLANE) * 2;

        #pragma unroll
        for (int k16 = 0; k16 < 2; k16++) {
            const int kb = k16 * 16;
            uint32_t aH[4][4], aL[4][4], bH[2][4], bL[2][4];
            #pragma unroll
            for (int i = 0; i < 4; i++) {
                const uint32_t off = (uint32_t)((wm * 64 + i * 16 + r8 + (sel & 1) * 8) * PITCH
                                                + kb + (sel >> 1) * 8) * 2;
                ldm_x4(aH[i][0], aH[i][1], aH[i][2], aH[i][3], pAh + off);
                ldm_x4(aL[i][0], aL[i][1], aL[i][2], aL[i][3], pAl + off);
            }
            #pragma unroll
            for (int jp = 0; jp < 2; jp++) {
                const uint32_t off = (uint32_t)(((wn * 32 + (jp * 2 + (sel >> 1)) * 8) + r8) * PITCH
                                                + kb + (sel & 1) * 8) * 2;
                ldm_x4(bH[jp][0], bH[jp][1], bH[jp][2], bH[jp][3], pBh + off);
                ldm_x4(bL[jp][0], bL[jp][1], bL[jp][2], bL[jp][3], pBl + off);
            }
            #pragma unroll
            for (int i = 0; i < 4; i++)
                #pragma unroll
                for (int j = 0; j < 4; j++) {
                    const uint32_t b0h = bH[j >> 1][(j & 1) * 2];
                    const uint32_t b1h = bH[j >> 1][(j & 1) * 2 + 1];
                    const uint32_t b0l = bL[j >> 1][(j & 1) * 2];
                    const uint32_t b1l = bL[j >> 1][(j & 1) * 2 + 1];
                    mma16816(c[i][j], aH[i][0], aH[i][1], aH[i][2], aH[i][3], b0h, b1h);
                    mma16816(c[i][j], aH[i][0], aH[i][1], aH[i][2], aH[i][3], b0l, b1l);
                    mma16816(c[i][j], aL[i][0], aL[i][1], aL[i][2], aL[i][3], b0h, b1h);
                }
        }
        __syncthreads();
        if (kc + 2 < 32) prefetch(kc + 2, buf);
    }
}

// ---------------------------------------------------------------------------
// QKV GEMM: epilogue emits fp16 q (split), k (single), v (split, transposed)
// ---------------------------------------------------------------------------
__global__ __launch_bounds__(256) void qkv_mma_kernel(const float* __restrict__ bias)
{
    const int m0 = blockIdx.y * 128, n0 = blockIdx.x * 128;
    float c[4][4][4];
    tc_gemm_mma(g_xhi, g_xlo, g_wqkv_hi, g_wqkv_lo, m0, n0, c);

    const int tid = threadIdx.x, wid = tid >> 5, lane = tid & 31;
    const int wm = wid & 1, wn = wid >> 1;
    const int qr = lane >> 2, qc = lane & 3;

    #pragma unroll
    for (int i = 0; i < 4; i++) {
        #pragma unroll
        for (int j = 0; j < 4; j++) {
            const int n = n0 + wn * 32 + j * 8 + qc * 2;
            const int part = n >> 10;
            const int h = (n & 1023) >> 6;
            const int e = n & 63;
            const float b0 = bias[n], b1 = bias[n + 1];
            #pragma unroll
            for (int half = 0; half < 2; half++) {
                const int m = m0 + wm * 64 + i * 16 + qr + half * 8;
                const int bb = m >> 9, t = m & 511;
                const int bh = bb * HH + h;
                float v0 = c[i][j][half * 2] + b0;
                float v1 = c[i][j][half * 2 + 1] + b1;
                if (part == 0) {
                    v0 *= QSCALE; v1 *= QSCALE;
                    float l0, l1;
                    uint32_t hi = packh_hi(v0, v1, l0, l1);
                    uint32_t lo = packh(l0, l1);
                    size_t off = ((size_t)bh * TT + t) * 64 + e;
                    *(uint32_t*)(g_qhi + off) = hi;
                    *(uint32_t*)(g_qlo + off) = lo;
                } else if (part == 1) {
                    size_t off = ((size_t)bh * SQ + LL + t) * 64 + e;
                    *(uint32_t*)(g_kf + off) = packh(v0, v1);
                } else {
                    __half h0 = __float2half_rn(v0);
                    __half h1 = __float2half_rn(v1);
                    __half l0 = __float2half_rn(v0 - __half2float(h0));
                    __half l1 = __float2half_rn(v1 - __half2float(h1));
                    size_t o0 = ((size_t)bh * 64 + e) * SQ + LL + t;
                    size_t o1 = ((size_t)bh * 64 + e + 1) * SQ + LL + t;
                    g_vthi[o0] = h0; g_vtlo[o0] = l0;
                    g_vthi[o1] = h1; g_vtlo[o1] = l1;
                }
            }
        }
    }
}

// ---------------------------------------------------------------------------
// Proj GEMM (unchanged bf16x3)
// ---------------------------------------------------------------------------
__global__ __launch_bounds__(256) void proj_mma_kernel(const float* __restrict__ bias,
                                                       float* __restrict__ out)
{
    const int m0 = blockIdx.y * 128, n0 = blockIdx.x * 128;
    float c[4][4][4];
    tc_gemm_mma(g_yhi, g_ylo, g_wp_hi, g_wp_lo, m0, n0, c);

    const int tid = threadIdx.x, wid = tid >> 5, lane = tid & 31;
    const int wm = wid & 1, wn = wid >> 1;
    const int qr = lane >> 2, qc = lane & 3;

    #pragma unroll
    for (int i = 0; i < 4; i++) {
        #pragma unroll
        for (int j = 0; j < 4; j++) {
            const int n = n0 + wn * 32 + j * 8 + qc * 2;
            const float b0 = bias[n], b1 = bias[n + 1];
            #pragma unroll
            for (int half = 0; half < 2; half++) {
                const int m = m0 + wm * 64 + i * 16 + qr + half * 8;
                float2 w = make_float2(c[i][j][half * 2] + b0,
                                       c[i][j][half * 2 + 1] + b1);
                *(float2*)&out[(size_t)m * 1024 + n] = w;
            }
        }
    }
}

// ---------------------------------------------------------------------------
// Flash attention, fp16x2: 64 queries/CTA, 128 threads, 3 CTA/SM.
// QK: (Qhi+Qlo)*Kf, 2 passes (K single fp16).  PV: Ph*(Vhi+Vlo), 2 passes
// (P single fp16).  Per-tile mma count 128 vs 192 for bf16x3.
// smem: 3 planes/stage (Kf, Vh, Vl).
// ---------------------------------------------------------------------------
#define APITCH 72
#define APLANE (64 * APITCH)           // halfwords per plane
#define ASTAGE (3 * APLANE)            // Kf, Vh, Vl
#define ATT_DYN_BYTES (2 * ASTAGE * 2) // 55296

__global__ __launch_bounds__(128, 3) void attn_mma_kernel()
{
    const int tid = threadIdx.x, wid = tid >> 5, lane = tid & 31;
    const int l4 = lane >> 2, qn = lane & 3;
    const int sel = lane >> 3, r8 = lane & 7;
    const int bh = blockIdx.y;
    const int qb = 7 - blockIdx.x;      // heavy blocks first
    const int base = qb * 64;

    const uint32_t sbase = (uint32_t)__cvta_generic_to_shared(dyn_smem);

    // Persistent Q fragments (pre-scaled fp16 hi/lo)
    uint32_t aQh[4][4], aQl[4][4];
    {
        const __half* qh = g_qhi + ((size_t)bh * TT + base + wid * 16) * 64;
        const __half* ql = g_qlo + ((size_t)bh * TT + base + wid * 16) * 64;
        #pragma unroll
        for (int kk = 0; kk < 4; kk++) {
            const int c0 = kk * 16 + qn * 2;
            aQh[kk][0] = *(const uint32_t*)(qh + l4 * 64 + c0);
            aQh[kk][1] = *(const uint32_t*)(qh + (l4 + 8) * 64 + c0);
            aQh[kk][2] = *(const uint32_t*)(qh + l4 * 64 + c0 + 8);
            aQh[kk][3] = *(const uint32_t*)(qh + (l4 + 8) * 64 + c0 + 8);
            aQl[kk][0] = *(const uint32_t*)(ql + l4 * 64 + c0);
            aQl[kk][1] = *(const uint32_t*)(ql + (l4 + 8) * 64 + c0);
            aQl[kk][2] = *(const uint32_t*)(ql + l4 * 64 + c0 + 8);
            aQl[kk][3] = *(const uint32_t*)(ql + (l4 + 8) * 64 + c0 + 8);
        }
    }

    float O[8][4];
    #pragma unroll
    for (int j = 0; j < 8; j++)
        #pragma unroll
        for (int t = 0; t < 4; t++) O[j][t] = 0.f;
    float mrow[2] = {-1e30f, -1e30f};
    float lrow[2] = {0.f, 0.f};

    const __half* Kf  = g_kf   + (size_t)bh * SQ * 64;
    const __half* Vth = g_vthi + (size_t)bh * 64 * SQ;
    const __half* Vtl = g_vtlo + (size_t)bh * 64 * SQ;

    const int n_tiles = 32 + qb + 1;

    auto prefetch = [&](int kt, int buf) {
        const int s0 = kt * 64;
        const uint32_t dst = sbase + (uint32_t)(buf * ASTAGE) * 2;
        #pragma unroll
        for (int i = 0; i < 4; i++) {
            const int idx = i * 128 + tid;        // [0,512)
            const int row = idx >> 3, seg = idx & 7;
            const uint32_t doff = (uint32_t)(row * APITCH + seg * 8) * 2;
            cpasync16(dst + doff,
                      Kf + (size_t)(s0 + row) * 64 + seg * 8);
            cpasync16(dst + (uint32_t)APLANE * 2 + doff,
                      Vth + (size_t)row * SQ + s0 + seg * 8);
            cpasync16(dst + (uint32_t)(2 * APLANE) * 2 + doff,
                      Vtl + (size_t)row * SQ + s0 + seg * 8);
        }
        CP_COMMIT();
    };

    prefetch(0, 0);
    if (n_tiles > 1) prefetch(1, 1);

    for (int kt = 0; kt < n_tiles; kt++) {
        const int buf = kt & 1;
        if (kt >= n_tiles - 1) { CP_WAIT0(); } else { CP_WAIT1(); }
        __syncthreads();

        const uint32_t ab  = sbase + (uint32_t)(buf * ASTAGE) * 2;
        const uint32_t pKf = ab;
        const uint32_t pVh = ab + (uint32_t)APLANE * 2;
        const uint32_t pVl = ab + (uint32_t)(2 * APLANE) * 2;

        // S = Q K^T (fp16x2: Qhi*K + Qlo*K)
        float Sc[8][4];
        #pragma unroll
        for (int j = 0; j < 8; j++)
            #pragma unroll
            for (int t = 0; t < 4; t++) Sc[j][t] = 0.f;

        #pragma unroll
        for (int kk = 0; kk < 4; kk++) {
            #pragma unroll
            for (int jp = 0; jp < 4; jp++) {
                const uint32_t off = (uint32_t)(((jp * 2 + (sel >> 1)) * 8 + r8) * APITCH
                                                + kk * 16 + (sel & 1) * 8) * 2;
                uint32_t kh[4];
                ldm_x4(kh[0], kh[1], kh[2], kh[3], pKf + off);
                #pragma unroll
                for (int jj = 0; jj < 2; jj++) {
                    const int j = jp * 2 + jj;
                    mma16816h(Sc[j], aQh[kk][0], aQh[kk][1], aQh[kk][2], aQh[kk][3],
                              kh[jj * 2], kh[jj * 2 + 1]);
                    mma16816h(Sc[j], aQl[kk][0], aQl[kk][1], aQl[kk][2], aQl[kk][3],
                              kh[jj * 2], kh[jj * 2 + 1]);
                }
            }
        }

        // Causal mask — only the final tile intersects the diagonal
        if (kt == n_tiles - 1) {
            #pragma unroll
            for (int j = 0; j < 8; j++)
                #pragma unroll
                for (int t = 0; t < 4; t++) {
                    const int col = j * 8 + qn * 2 + (t & 1);
                    const int row = wid * 16 + l4 + ((t >> 1) << 3);
                    if (col > row) Sc[j][t] = -1e30f;
                }
        }

        // Online softmax (per row-half; 4-lane shfl reductions)
        #pragma unroll
        for (int h = 0; h < 2; h++) {
            float mt = -1e30f;
            #pragma unroll
            for (int j = 0; j < 8; j++)
                mt = fmaxf(mt, fmaxf(Sc[j][2 * h], Sc[j][2 * h + 1]));
            mt = fmaxf(mt, __shfl_xor_sync(0xffffffffu, mt, 1));
            mt = fmaxf(mt, __shfl_xor_sync(0xffffffffu, mt, 2));
            const float mn = fmaxf(mrow[h], mt);
            const float alpha = ex2(mrow[h] - mn);
            mrow[h] = mn;
            float ls = 0.f;
            #pragma unroll
            for (int j = 0; j < 8; j++) {
                float p0 = ex2(Sc[j][2 * h] - mn);
                float p1 = ex2(Sc[j][2 * h + 1] - mn);
                Sc[j][2 * h] = p0; Sc[j][2 * h + 1] = p1;
                ls += p0 + p1;
            }
            ls += __shfl_xor_sync(0xffffffffu, ls, 1);
            ls += __shfl_xor_sync(0xffffffffu, ls, 2);
            lrow[h] = lrow[h] * alpha + ls;
            #pragma unroll
            for (int j = 0; j < 8; j++) {
                O[j][2 * h] *= alpha; O[j][2 * h + 1] *= alpha;
            }
        }

        // Pack P -> fp16 A fragments (single precision class; error 2^-11)
        uint32_t aPh[4][4];
        #pragma unroll
        for (int kk = 0; kk < 4; kk++) {
            const int j0 = 2 * kk, j1 = 2 * kk + 1;
            aPh[kk][0] = packh(Sc[j0][0], Sc[j0][1]);
            aPh[kk][1] = packh(Sc[j0][2], Sc[j0][3]);
            aPh[kk][2] = packh(Sc[j1][0], Sc[j1][1]);
            aPh[kk][3] = packh(Sc[j1][2], Sc[j1][3]);
        }

        // O += P V (fp16x2: P*Vhi + P*Vlo)
        #pragma unroll
        for (int kk = 0; kk < 4; kk++) {
            #pragma unroll
            for (int jp = 0; jp < 4; jp++) {
                const uint32_t off = (uint32_t)(((jp * 2 + (sel >> 1)) * 8 + r8) * APITCH
                                                + kk * 16 + (sel & 1) * 8) * 2;
                uint32_t vh[4], vl[4];
                ldm_x4(vh[0], vh[1], vh[2], vh[3], pVh + off);
                ldm_x4(vl[0], vl[1], vl[2], vl[3], pVl + off);
                #pragma unroll
                for (int jj = 0; jj < 2; jj++) {
                    const int j = jp * 2 + jj;
                    mma16816h(O[j], aPh[kk][0], aPh[kk][1], aPh[kk][2], aPh[kk][3],
                              vh[jj * 2], vh[jj * 2 + 1]);
                    mma16816h(O[j], aPh[kk][0], aPh[kk][1], aPh[kk][2], aPh[kk][3],
                              vl[jj * 2], vl[jj * 2 + 1]);
                }
            }
        }

        __syncthreads();
        if (kt + 2 < n_tiles) prefetch(kt + 2, buf);
    }

    // Epilogue: y = O / l -> bf16-split proj input
    const int b = bh >> 4, hh = bh & 15;
    #pragma unroll
    for (int h = 0; h < 2; h++) {
        const int t = base + wid * 16 + l4 + h * 8;
        const float inv = 1.f / lrow[h];
        #pragma unroll
        for (int j = 0; j < 8; j++) {
            const float y0 = O[j][2 * h] * inv;
            const float y1 = O[j][2 * h + 1] * inv;
            float l0, l1;
            uint32_t hi = pack_hi(y0, y1, l0, l1);
            uint32_t lo = pack_bf(l0, l1);
            const size_t off = ((size_t)(b * TT + t)) * CC + hh * 64 + j * 8 + qn * 2;
            *(uint32_t*)(g_yhi + off) = hi;
            *(uint32_t*)(g_ylo + off) = lo;
        }
    }
}

// ---------------------------------------------------------------------------
// Fused prep kernel: x/weights -> bf16 splits; K cache -> single fp16;
// V cache -> transposed fp16 hi/lo.
// ---------------------------------------------------------------------------
#define NB_XS 4096
#define NB_WQ 3072
#define NB_WP 1024
#define NB_KC 16384
#define NB_VC 16384
#define NB_TOTAL (NB_XS + NB_WQ + NB_WP + NB_KC + NB_VC)

__global__ __launch_bounds__(256) void prep_fused(
    const float* __restrict__ x,
    const float* __restrict__ kc,
    const float* __restrict__ vc,
    const float* __restrict__ Wqkv,
    const float* __restrict__ Wproj)
{
    __shared__ float tile[32][33];
    const int bid = blockIdx.x;
    const int tid = threadIdx.x;

    if (bid < NB_XS) {
        const int i = bid * 256 + tid;
        float4 v = ((const float4*)x)[i];
        __nv_bfloat16 hh[4], ll[4];
        float a[4] = {v.x, v.y, v.z, v.w};
        #pragma unroll
        for (int j = 0; j < 4; j++) {
            hh[j] = __float2bfloat16_rn(a[j]);
            ll[j] = __float2bfloat16_rn(a[j] - __bfloat162float(hh[j]));
        }
        ((uint2*)g_xhi)[i] = *(uint2*)hh;
        ((uint2*)g_xlo)[i] = *(uint2*)ll;
    } else if (bid < NB_XS + NB_WQ + NB_WP) {
        const float* W;
        __nv_bfloat16 *hi, *lo;
        int f, N;
        if (bid < NB_XS + NB_WQ) {
            f = bid - NB_XS; W = Wqkv; hi = g_wqkv_hi; lo = g_wqkv_lo; N = 3072;
        } else {
            f = bid - NB_XS - NB_WQ; W = Wproj; hi = g_wp_hi; lo = g_wp_lo; N = 1024;
        }
        const int ntx = N / 32;
        const int nx = (f % ntx) * 32, kx = (f / ntx) * 32;
        const int tx = tid & 31, ty = tid >> 5;
        #pragma unroll
        for (int r = ty; r < 32; r += 8)
            tile[r][tx] = W[(size_t)(kx + r) * N + nx + tx];
        __syncthreads();
        #pragma unroll
        for (int r = ty; r < 32; r += 8) {
            float xx = tile[tx][r];
            __nv_bfloat16 h = __float2bfloat16_rn(xx);
            __nv_bfloat16 l = __float2bfloat16_rn(xx - __bfloat162float(h));
            size_t o = (size_t)(nx + r) * 1024 + kx + tx;
            hi[o] = h;
            lo[o] = l;
        }
    } else if (bid < NB_XS + NB_WQ + NB_WP + NB_KC) {
        // ---- K cache -> single fp16 ----
        const size_t i = (size_t)(bid - NB_XS - NB_WQ - NB_WP) * 256 + tid;
        float4 v = ((const float4*)kc)[i];
        const size_t flat = i * 4;
        const size_t bh = flat >> 17;
        const size_t rem = flat & 131071;
        const size_t s = rem >> 6, e = rem & 63;
        __half hv[4];
        float a[4] = {v.x, v.y, v.z, v.w};
        #pragma unroll
        for (int j = 0; j < 4; j++) hv[j] = __float2half_rn(a[j]);
        const size_t off = (bh * SQ + s) * 64 + e;
        *(uint2*)(g_kf + off) = *(uint2*)hv;
    } else {
        // ---- V cache -> transposed fp16 hi/lo ----
        const int f = bid - NB_XS - NB_WQ - NB_WP - NB_KC;
        const int sx = f & 63;
        const int ey = (f >> 6) & 1;
        const int bh = f >> 7;
        const int s0 = sx * 32, e0 = ey * 32;
        const int tx = tid & 31, ty = tid >> 5;
        #pragma unroll
        for (int r = ty; r < 32; r += 8)
            tile[r][tx] = vc[((size_t)bh * LL + s0 + r) * 64 + e0 + tx];
        __syncthreads();
        #pragma unroll
        for (int r = ty; r < 32; r += 8) {
            float xx = tile[tx][r];
            __half h = __float2half_rn(xx);
            __half l = __float2half_rn(xx - __half2float(h));
            const size_t off = ((size_t)bh * 64 + e0 + r) * SQ + s0 + tx;
            g_vthi[off] = h;
            g_vtlo[off] = l;
        }
    }
}

// ---------------------------------------------------------------------------
extern "C" void kernel_launch(void* const* d_in, const int* in_sizes, int n_in,
                              void* d_out, int out_size) {
    const float* x       = (const float*)d_in[0];
    const float* k_cache = (const float*)d_in[1];
    const float* v_cache = (const float*)d_in[2];
    const float* Wqkv    = (const float*)d_in[3];
    const float* bqkv    = (const float*)d_in[4];
    const float* Wproj   = (const float*)d_in[5];
    const float* bproj   = (const float*)d_in[6];
    float* out           = (float*)d_out;

    cudaFuncSetAttribute(qkv_mma_kernel, cudaFuncAttributeMaxDynamicSharedMemorySize,
                         GEMM_DYN_BYTES);
    cudaFuncSetAttribute(proj_mma_kernel, cudaFuncAttributeMaxDynamicSharedMemorySize,
                         GEMM_DYN_BYTES);
    cudaFuncSetAttribute(attn_mma_kernel, cudaFuncAttributeMaxDynamicSharedMemorySize,
                         ATT_DYN_BYTES);

    prep_fused<<<NB_TOTAL, 256>>>(x, k_cache, v_cache, Wqkv, Wproj);

    qkv_mma_kernel<<<dim3(24, 32), 256, GEMM_DYN_BYTES>>>(bqkv);
    attn_mma_kernel<<<dim3(8, 128), 128, ATT_DYN_BYTES>>>();
    proj_mma_kernel<<<dim3(8, 32), 256, GEMM_DYN_BYTES>>>(bproj, out);
}

// round 17
// speedup vs baseline: 2.0992x; 1.1452x over previous
#include <cuda_runtime.h>
#include <cuda_bf16.h>
#include <cuda_fp16.h>
#include <cstdint>
#include <math.h>

#define BB 8
#define TT 512
#define CC 1024
#define HH 16
#define EE 64
#define LL 2048
#define SQ 2560                     // L + T
#define QSCALE 0.1803368801111244f  // 0.125 * log2(e)

// ---------------------------------------------------------------------------
// Scratch (__device__ globals; no allocation allowed)
// ---------------------------------------------------------------------------
__device__ __half g_xh16[BB*TT*CC];            // x split, fp16 hi
__device__ __half g_xl16[BB*TT*CC];            // x split, fp16 lo
__device__ __half g_wqh [3*CC*CC];             // Wqkv [N=3072][K=1024], single fp16
__device__ __nv_bfloat16 g_yhi[BB*TT*CC];
__device__ __nv_bfloat16 g_ylo[BB*TT*CC];
__device__ __nv_bfloat16 g_wp_hi[CC*CC];       // [N=1024][K=1024]
__device__ __nv_bfloat16 g_wp_lo[CC*CC];

// Attention operands in fp16 (11-bit mantissa -> 2-pass schemes)
__device__ __half g_qhi[BB*HH*TT*EE];   // [bh][t][e], pre-scaled, fp16 hi
__device__ __half g_qlo[BB*HH*TT*EE];   // fp16 lo
__device__ __half g_kf [BB*HH*SQ*EE];   // [bh][s][e], SINGLE fp16
__device__ __half g_vthi[BB*HH*EE*SQ];  // [bh][e][s] transposed, fp16 hi
__device__ __half g_vtlo[BB*HH*EE*SQ];  // fp16 lo

// ---------------------------------------------------------------------------
// Helpers
// ---------------------------------------------------------------------------
__device__ __forceinline__ void mma16816(float c[4],
    uint32_t a0, uint32_t a1, uint32_t a2, uint32_t a3,
    uint32_t b0, uint32_t b1)
{
    asm volatile(
        "mma.sync.aligned.m16n8k16.row.col.f32.bf16.bf16.f32 "
        "{%0,%1,%2,%3}, {%4,%5,%6,%7}, {%8,%9}, {%0,%1,%2,%3};"
        : "+f"(c[0]), "+f"(c[1]), "+f"(c[2]), "+f"(c[3])
        : "r"(a0), "r"(a1), "r"(a2), "r"(a3), "r"(b0), "r"(b1));
}
__device__ __forceinline__ void mma16816h(float c[4],
    uint32_t a0, uint32_t a1, uint32_t a2, uint32_t a3,
    uint32_t b0, uint32_t b1)
{
    asm volatile(
        "mma.sync.aligned.m16n8k16.row.col.f32.f16.f16.f32 "
        "{%0,%1,%2,%3}, {%4,%5,%6,%7}, {%8,%9}, {%0,%1,%2,%3};"
        : "+f"(c[0]), "+f"(c[1]), "+f"(c[2]), "+f"(c[3])
        : "r"(a0), "r"(a1), "r"(a2), "r"(a3), "r"(b0), "r"(b1));
}
__device__ __forceinline__ void ldm_x4(uint32_t& r0, uint32_t& r1,
                                       uint32_t& r2, uint32_t& r3, uint32_t addr)
{
    asm volatile("ldmatrix.sync.aligned.m8n8.x4.shared.b16 {%0,%1,%2,%3}, [%4];"
        : "=r"(r0), "=r"(r1), "=r"(r2), "=r"(r3) : "r"(addr));
}
__device__ __forceinline__ void cpasync16(uint32_t dst, const void* src) {
    asm volatile("cp.async.cg.shared.global [%0], [%1], 16;"
        :: "r"(dst), "l"(src) : "memory");
}
#define CP_COMMIT() asm volatile("cp.async.commit_group;" ::: "memory")
#define CP_WAIT1()  asm volatile("cp.async.wait_group 1;" ::: "memory")
#define CP_WAIT0()  asm volatile("cp.async.wait_group 0;" ::: "memory")

__device__ __forceinline__ float ex2(float x) {
    float r; asm("ex2.approx.ftz.f32 %0, %1;" : "=f"(r) : "f"(x)); return r;
}
__device__ __forceinline__ uint32_t pack_hi(float a, float b, float& ra, float& rb) {
    __nv_bfloat162 h = __floats2bfloat162_rn(a, b);
    ra = a - __low2float(h); rb = b - __high2float(h);
    return *(uint32_t*)&h;
}
__device__ __forceinline__ uint32_t pack_bf(float a, float b) {
    __nv_bfloat162 h = __floats2bfloat162_rn(a, b);
    return *(uint32_t*)&h;
}
__device__ __forceinline__ uint32_t packh_hi(float a, float b, float& ra, float& rb) {
    __half2 h = __floats2half2_rn(a, b);
    ra = a - __low2float(h); rb = b - __high2float(h);
    return *(uint32_t*)&h;
}
__device__ __forceinline__ uint32_t packh(float a, float b) {
    __half2 h = __floats2half2_rn(a, b);
    return *(uint32_t*)&h;
}

// ---------------------------------------------------------------------------
// Shared tiling constants
// ---------------------------------------------------------------------------
#define PITCH 40
#define PLANE (128 * PITCH)

extern __shared__ __nv_bfloat16 dyn_smem[];

// ---------------------------------------------------------------------------
// fp16x2 GEMM core (QKV): A = x hi/lo fp16, B = W single fp16.
// 3 planes/stage, 2 passes per k16. 61440 B dynamic smem.
// ---------------------------------------------------------------------------
#define HSTAGE (3 * PLANE)
#define QKV_DYN_BYTES (2 * HSTAGE * 2)   // 61440

__device__ __forceinline__ void tc_gemm_h2(
    const __half* __restrict__ Ahi, const __half* __restrict__ Alo,
    const __half* __restrict__ B,
    int m0, int n0, float c[4][4][4])
{
    const int tid = threadIdx.x;
    const int wid = tid >> 5, lane = tid & 31;
    const int wm = wid & 1, wn = wid >> 1;
    const int sel = lane >> 3, r8 = lane & 7;

    #pragma unroll
    for (int i = 0; i < 4; i++)
        #pragma unroll
        for (int j = 0; j < 4; j++)
            #pragma unroll
            for (int t = 0; t < 4; t++) c[i][j][t] = 0.f;

    const uint32_t sbase = (uint32_t)__cvta_generic_to_shared(dyn_smem);
    const __half* planes[3] = {Ahi, Alo, B};

    auto prefetch = [&](int kc, int buf) {
        const int k0 = kc * 32;
        #pragma unroll
        for (int p = 0; p < 3; p++) {
            const __half* src = planes[p];
            const int br = (p < 2) ? m0 : n0;
            const uint32_t dplane = sbase + (uint32_t)(buf * HSTAGE + p * PLANE) * 2;
            #pragma unroll
            for (int i = 0; i < 2; i++) {
                const int idx = i * 256 + tid;        // [0,512)
                const int row = idx >> 2, seg = idx & 3;
                cpasync16(dplane + (uint32_t)(row * PITCH + seg * 8) * 2,
                          src + (size_t)(br + row) * 1024 + k0 + seg * 8);
            }
        }
        CP_COMMIT();
    };

    prefetch(0, 0);
    prefetch(1, 1);

    for (int kc = 0; kc < 32; kc++) {
        const int buf = kc & 1;
        if (kc == 31) { CP_WAIT0(); } else { CP_WAIT1(); }
        __syncthreads();

        const uint32_t ab  = sbase + (uint32_t)(buf * HSTAGE) * 2;
        const uint32_t pAh = ab;
        const uint32_t pAl = ab + (uint32_t)PLANE * 2;
        const uint32_t pB  = ab + (uint32_t)(2 * PLANE) * 2;

        #pragma unroll
        for (int k16 = 0; k16 < 2; k16++) {
            const int kb = k16 * 16;
            uint32_t aH[4][4], aL[4][4], bF[2][4];
            #pragma unroll
            for (int i = 0; i < 4; i++) {
                const uint32_t off = (uint32_t)((wm * 64 + i * 16 + r8 + (sel & 1) * 8) * PITCH
                                                + kb + (sel >> 1) * 8) * 2;
                ldm_x4(aH[i][0], aH[i][1], aH[i][2], aH[i][3], pAh + off);
                ldm_x4(aL[i][0], aL[i][1], aL[i][2], aL[i][3], pAl + off);
            }
            #pragma unroll
            for (int jp = 0; jp < 2; jp++) {
                const uint32_t off = (uint32_t)(((wn * 32 + (jp * 2 + (sel >> 1)) * 8) + r8) * PITCH
                                                + kb + (sel & 1) * 8) * 2;
                ldm_x4(bF[jp][0], bF[jp][1], bF[jp][2], bF[jp][3], pB + off);
            }
            #pragma unroll
            for (int i = 0; i < 4; i++)
                #pragma unroll
                for (int j = 0; j < 4; j++) {
                    const uint32_t b0 = bF[j >> 1][(j & 1) * 2];
                    const uint32_t b1 = bF[j >> 1][(j & 1) * 2 + 1];
                    mma16816h(c[i][j], aH[i][0], aH[i][1], aH[i][2], aH[i][3], b0, b1);
                    mma16816h(c[i][j], aL[i][0], aL[i][1], aL[i][2], aL[i][3], b0, b1);
                }
        }
        __syncthreads();
        if (kc + 2 < 32) prefetch(kc + 2, buf);
    }
}

// ---------------------------------------------------------------------------
// bf16x3 GEMM core (proj, unchanged)
// ---------------------------------------------------------------------------
#define GSTAGE (4 * PLANE)
#define GEMM_DYN_BYTES (2 * GSTAGE * 2)   // 81920

__device__ __forceinline__ void tc_gemm_mma(
    const __nv_bfloat16* __restrict__ Ahi, const __nv_bfloat16* __restrict__ Alo,
    const __nv_bfloat16* __restrict__ Bhi, const __nv_bfloat16* __restrict__ Blo,
    int m0, int n0, float c[4][4][4])
{
    const int tid = threadIdx.x;
    const int wid = tid >> 5, lane = tid & 31;
    const int wm = wid & 1, wn = wid >> 1;
    const int sel = lane >> 3, r8 = lane & 7;

    #pragma unroll
    for (int i = 0; i < 4; i++)
        #pragma unroll
        for (int j = 0; j < 4; j++)
            #pragma unroll
            for (int t = 0; t < 4; t++) c[i][j][t] = 0.f;

    const uint32_t sbase = (uint32_t)__cvta_generic_to_shared(dyn_smem);
    const __nv_bfloat16* planes[4] = {Ahi, Alo, Bhi, Blo};

    auto prefetch = [&](int kc, int buf) {
        const int k0 = kc * 32;
        #pragma unroll
        for (int p = 0; p < 4; p++) {
            const __nv_bfloat16* src = planes[p];
            const int br = (p < 2) ? m0 : n0;
            const uint32_t dplane = sbase + (uint32_t)(buf * GSTAGE + p * PLANE) * 2;
            #pragma unroll
            for (int i = 0; i < 2; i++) {
                const int idx = i * 256 + tid;
                const int row = idx >> 2, seg = idx & 3;
                cpasync16(dplane + (uint32_t)(row * PITCH + seg * 8) * 2,
                          src + (size_t)(br + row) * 1024 + k0 + seg * 8);
            }
        }
        CP_COMMIT();
    };

    prefetch(0, 0);
    prefetch(1, 1);

    for (int kc = 0; kc < 32; kc++) {
        const int buf = kc & 1;
        if (kc == 31) { CP_WAIT0(); } else { CP_WAIT1(); }
        __syncthreads();

        const uint32_t ab  = sbase + (uint32_t)(buf * GSTAGE) * 2;
        const uint32_t pAh = ab;
        const uint32_t pAl = ab + (uint32_t)PLANE * 2;
        const uint32_t pBh = ab + (uint32_t)(2 * PLANE) * 2;
        const uint32_t pBl = ab + (uint32_t)(3 * PLANE) * 2;

        #pragma unroll
        for (int k16 = 0; k16 < 2; k16++) {
            const int kb = k16 * 16;
            uint32_t aH[4][4], aL[4][4], bH[2][4], bL[2][4];
            #pragma unroll
            for (int i = 0; i < 4; i++) {
                const uint32_t off = (uint32_t)((wm * 64 + i * 16 + r8 + (sel & 1) * 8) * PITCH
                                                + kb + (sel >> 1) * 8) * 2;
                ldm_x4(aH[i][0], aH[i][1], aH[i][2], aH[i][3], pAh + off);
                ldm_x4(aL[i][0], aL[i][1], aL[i][2], aL[i][3], pAl + off);
            }
            #pragma unroll
            for (int jp = 0; jp < 2; jp++) {
                const uint32_t off = (uint32_t)(((wn * 32 + (jp * 2 + (sel >> 1)) * 8) + r8) * PITCH
                                                + kb + (sel & 1) * 8) * 2;
                ldm_x4(bH[jp][0], bH[jp][1], bH[jp][2], bH[jp][3], pBh + off);
                ldm_x4(bL[jp][0], bL[jp][1], bL[jp][2], bL[jp][3], pBl + off);
            }
            #pragma unroll
            for (int i = 0; i < 4; i++)
                #pragma unroll
                for (int j = 0; j < 4; j++) {
                    const uint32_t b0h = bH[j >> 1][(j & 1) * 2];
                    const uint32_t b1h = bH[j >> 1][(j & 1) * 2 + 1];
                    const uint32_t b0l = bL[j >> 1][(j & 1) * 2];
                    const uint32_t b1l = bL[j >> 1][(j & 1) * 2 + 1];
                    mma16816(c[i][j], aH[i][0], aH[i][1], aH[i][2], aH[i][3], b0h, b1h);
                    mma16816(c[i][j], aH[i][0], aH[i][1], aH[i][2], aH[i][3], b0l, b1l);
                    mma16816(c[i][j], aL[i][0], aL[i][1], aL[i][2], aL[i][3], b0h, b1h);
                }
        }
        __syncthreads();
        if (kc + 2 < 32) prefetch(kc + 2, buf);
    }
}

// ---------------------------------------------------------------------------
// QKV GEMM (fp16x2): epilogue emits fp16 q (split), k (single), v (split,T)
// ---------------------------------------------------------------------------
__global__ __launch_bounds__(256) void qkv_mma_kernel(const float* __restrict__ bias)
{
    const int m0 = blockIdx.y * 128, n0 = blockIdx.x * 128;
    float c[4][4][4];
    tc_gemm_h2(g_xh16, g_xl16, g_wqh, m0, n0, c);

    const int tid = threadIdx.x, wid = tid >> 5, lane = tid & 31;
    const int wm = wid & 1, wn = wid >> 1;
    const int qr = lane >> 2, qc = lane & 3;

    #pragma unroll
    for (int i = 0; i < 4; i++) {
        #pragma unroll
        for (int j = 0; j < 4; j++) {
            const int n = n0 + wn * 32 + j * 8 + qc * 2;
            const int part = n >> 10;
            const int h = (n & 1023) >> 6;
            const int e = n & 63;
            const float b0 = bias[n], b1 = bias[n + 1];
            #pragma unroll
            for (int half = 0; half < 2; half++) {
                const int m = m0 + wm * 64 + i * 16 + qr + half * 8;
                const int bb = m >> 9, t = m & 511;
                const int bh = bb * HH + h;
                float v0 = c[i][j][half * 2] + b0;
                float v1 = c[i][j][half * 2 + 1] + b1;
                if (part == 0) {
                    v0 *= QSCALE; v1 *= QSCALE;
                    float l0, l1;
                    uint32_t hi = packh_hi(v0, v1, l0, l1);
                    uint32_t lo = packh(l0, l1);
                    size_t off = ((size_t)bh * TT + t) * 64 + e;
                    *(uint32_t*)(g_qhi + off) = hi;
                    *(uint32_t*)(g_qlo + off) = lo;
                } else if (part == 1) {
                    size_t off = ((size_t)bh * SQ + LL + t) * 64 + e;
                    *(uint32_t*)(g_kf + off) = packh(v0, v1);
                } else {
                    __half h0 = __float2half_rn(v0);
                    __half h1 = __float2half_rn(v1);
                    __half l0 = __float2half_rn(v0 - __half2float(h0));
                    __half l1 = __float2half_rn(v1 - __half2float(h1));
                    size_t o0 = ((size_t)bh * 64 + e) * SQ + LL + t;
                    size_t o1 = ((size_t)bh * 64 + e + 1) * SQ + LL + t;
                    g_vthi[o0] = h0; g_vtlo[o0] = l0;
                    g_vthi[o1] = h1; g_vtlo[o1] = l1;
                }
            }
        }
    }
}

// ---------------------------------------------------------------------------
// Proj GEMM (unchanged bf16x3)
// ---------------------------------------------------------------------------
__global__ __launch_bounds__(256) void proj_mma_kernel(const float* __restrict__ bias,
                                                       float* __restrict__ out)
{
    const int m0 = blockIdx.y * 128, n0 = blockIdx.x * 128;
    float c[4][4][4];
    tc_gemm_mma(g_yhi, g_ylo, g_wp_hi, g_wp_lo, m0, n0, c);

    const int tid = threadIdx.x, wid = tid >> 5, lane = tid & 31;
    const int wm = wid & 1, wn = wid >> 1;
    const int qr = lane >> 2, qc = lane & 3;

    #pragma unroll
    for (int i = 0; i < 4; i++) {
        #pragma unroll
        for (int j = 0; j < 4; j++) {
            const int n = n0 + wn * 32 + j * 8 + qc * 2;
            const float b0 = bias[n], b1 = bias[n + 1];
            #pragma unroll
            for (int half = 0; half < 2; half++) {
                const int m = m0 + wm * 64 + i * 16 + qr + half * 8;
                float2 w = make_float2(c[i][j][half * 2] + b0,
                                       c[i][j][half * 2 + 1] + b1);
                *(float2*)&out[(size_t)m * 1024 + n] = w;
            }
        }
    }
}

// ---------------------------------------------------------------------------
// Flash attention, fp16x2 (unchanged 610us body)
// ---------------------------------------------------------------------------
#define APITCH 72
#define APLANE (64 * APITCH)
#define ASTAGE (3 * APLANE)            // Kf, Vh, Vl
#define ATT_DYN_BYTES (2 * ASTAGE * 2) // 55296

__global__ __launch_bounds__(128, 3) void attn_mma_kernel()
{
    const int tid = threadIdx.x, wid = tid >> 5, lane = tid & 31;
    const int l4 = lane >> 2, qn = lane & 3;
    const int sel = lane >> 3, r8 = lane & 7;
    const int bh = blockIdx.y;
    const int qb = 7 - blockIdx.x;
    const int base = qb * 64;

    const uint32_t sbase = (uint32_t)__cvta_generic_to_shared(dyn_smem);

    uint32_t aQh[4][4], aQl[4][4];
    {
        const __half* qh = g_qhi + ((size_t)bh * TT + base + wid * 16) * 64;
        const __half* ql = g_qlo + ((size_t)bh * TT + base + wid * 16) * 64;
        #pragma unroll
        for (int kk = 0; kk < 4; kk++) {
            const int c0 = kk * 16 + qn * 2;
            aQh[kk][0] = *(const uint32_t*)(qh + l4 * 64 + c0);
            aQh[kk][1] = *(const uint32_t*)(qh + (l4 + 8) * 64 + c0);
            aQh[kk][2] = *(const uint32_t*)(qh + l4 * 64 + c0 + 8);
            aQh[kk][3] = *(const uint32_t*)(qh + (l4 + 8) * 64 + c0 + 8);
            aQl[kk][0] = *(const uint32_t*)(ql + l4 * 64 + c0);
            aQl[kk][1] = *(const uint32_t*)(ql + (l4 + 8) * 64 + c0);
            aQl[kk][2] = *(const uint32_t*)(ql + l4 * 64 + c0 + 8);
            aQl[kk][3] = *(const uint32_t*)(ql + (l4 + 8) * 64 + c0 + 8);
        }
    }

    float O[8][4];
    #pragma unroll
    for (int j = 0; j < 8; j++)
        #pragma unroll
        for (int t = 0; t < 4; t++) O[j][t] = 0.f;
    float mrow[2] = {-1e30f, -1e30f};
    float lrow[2] = {0.f, 0.f};

    const __half* Kf  = g_kf   + (size_t)bh * SQ * 64;
    const __half* Vth = g_vthi + (size_t)bh * 64 * SQ;
    const __half* Vtl = g_vtlo + (size_t)bh * 64 * SQ;

    const int n_tiles = 32 + qb + 1;

    auto prefetch = [&](int kt, int buf) {
        const int s0 = kt * 64;
        const uint32_t dst = sbase + (uint32_t)(buf * ASTAGE) * 2;
        #pragma unroll
        for (int i = 0; i < 4; i++) {
            const int idx = i * 128 + tid;
            const int row = idx >> 3, seg = idx & 7;
            const uint32_t doff = (uint32_t)(row * APITCH + seg * 8) * 2;
            cpasync16(dst + doff,
                      Kf + (size_t)(s0 + row) * 64 + seg * 8);
            cpasync16(dst + (uint32_t)APLANE * 2 + doff,
                      Vth + (size_t)row * SQ + s0 + seg * 8);
            cpasync16(dst + (uint32_t)(2 * APLANE) * 2 + doff,
                      Vtl + (size_t)row * SQ + s0 + seg * 8);
        }
        CP_COMMIT();
    };

    prefetch(0, 0);
    if (n_tiles > 1) prefetch(1, 1);

    for (int kt = 0; kt < n_tiles; kt++) {
        const int buf = kt & 1;
        if (kt >= n_tiles - 1) { CP_WAIT0(); } else { CP_WAIT1(); }
        __syncthreads();

        const uint32_t ab  = sbase + (uint32_t)(buf * ASTAGE) * 2;
        const uint32_t pKf = ab;
        const uint32_t pVh = ab + (uint32_t)APLANE * 2;
        const uint32_t pVl = ab + (uint32_t)(2 * APLANE) * 2;

        float Sc[8][4];
        #pragma unroll
        for (int j = 0; j < 8; j++)
            #pragma unroll
            for (int t = 0; t < 4; t++) Sc[j][t] = 0.f;

        #pragma unroll
        for (int kk = 0; kk < 4; kk++) {
            #pragma unroll
            for (int jp = 0; jp < 4; jp++) {
                const uint32_t off = (uint32_t)(((jp * 2 + (sel >> 1)) * 8 + r8) * APITCH
                                                + kk * 16 + (sel & 1) * 8) * 2;
                uint32_t kh[4];
                ldm_x4(kh[0], kh[1], kh[2], kh[3], pKf + off);
                #pragma unroll
                for (int jj = 0; jj < 2; jj++) {
                    const int j = jp * 2 + jj;
                    mma16816h(Sc[j], aQh[kk][0], aQh[kk][1], aQh[kk][2], aQh[kk][3],
                              kh[jj * 2], kh[jj * 2 + 1]);
                    mma16816h(Sc[j], aQl[kk][0], aQl[kk][1], aQl[kk][2], aQl[kk][3],
                              kh[jj * 2], kh[jj * 2 + 1]);
                }
            }
        }

        if (kt == n_tiles - 1) {
            #pragma unroll
            for (int j = 0; j < 8; j++)
                #pragma unroll
                for (int t = 0; t < 4; t++) {
                    const int col = j * 8 + qn * 2 + (t & 1);
                    const int row = wid * 16 + l4 + ((t >> 1) << 3);
                    if (col > row) Sc[j][t] = -1e30f;
                }
        }

        #pragma unroll
        for (int h = 0; h < 2; h++) {
            float mt = -1e30f;
            #pragma unroll
            for (int j = 0; j < 8; j++)
                mt = fmaxf(mt, fmaxf(Sc[j][2 * h], Sc[j][2 * h + 1]));
            mt = fmaxf(mt, __shfl_xor_sync(0xffffffffu, mt, 1));
            mt = fmaxf(mt, __shfl_xor_sync(0xffffffffu, mt, 2));
            const float mn = fmaxf(mrow[h], mt);
            const float alpha = ex2(mrow[h] - mn);
            mrow[h] = mn;
            float ls = 0.f;
            #pragma unroll
            for (int j = 0; j < 8; j++) {
                float p0 = ex2(Sc[j][2 * h] - mn);
                float p1 = ex2(Sc[j][2 * h + 1] - mn);
                Sc[j][2 * h] = p0; Sc[j][2 * h + 1] = p1;
                ls += p0 + p1;
            }
            ls += __shfl_xor_sync(0xffffffffu, ls, 1);
            ls += __shfl_xor_sync(0xffffffffu, ls, 2);
            lrow[h] = lrow[h] * alpha + ls;
            #pragma unroll
            for (int j = 0; j < 8; j++) {
                O[j][2 * h] *= alpha; O[j][2 * h + 1] *= alpha;
            }
        }

        uint32_t aPh[4][4];
        #pragma unroll
        for (int kk = 0; kk < 4; kk++) {
            const int j0 = 2 * kk, j1 = 2 * kk + 1;
            aPh[kk][0] = packh(Sc[j0][0], Sc[j0][1]);
            aPh[kk][1] = packh(Sc[j0][2], Sc[j0][3]);
            aPh[kk][2] = packh(Sc[j1][0], Sc[j1][1]);
            aPh[kk][3] = packh(Sc[j1][2], Sc[j1][3]);
        }

        #pragma unroll
        for (int kk = 0; kk < 4; kk++) {
            #pragma unroll
            for (int jp = 0; jp < 4; jp++) {
                const uint32_t off = (uint32_t)(((jp * 2 + (sel >> 1)) * 8 + r8) * APITCH
                                                + kk * 16 + (sel & 1) * 8) * 2;
                uint32_t vh[4], vl[4];
                ldm_x4(vh[0], vh[1], vh[2], vh[3], pVh + off);
                ldm_x4(vl[0], vl[1], vl[2], vl[3], pVl + off);
                #pragma unroll
                for (int jj = 0; jj < 2; jj++) {
                    const int j = jp * 2 + jj;
                    mma16816h(O[j], aPh[kk][0], aPh[kk][1], aPh[kk][2], aPh[kk][3],
                              vh[jj * 2], vh[jj * 2 + 1]);
                    mma16816h(O[j], aPh[kk][0], aPh[kk][1], aPh[kk][2], aPh[kk][3],
                              vl[jj * 2], vl[jj * 2 + 1]);
                }
            }
        }

        __syncthreads();
        if (kt + 2 < n_tiles) prefetch(kt + 2, buf);
    }

    const int b = bh >> 4, hh = bh & 15;
    #pragma unroll
    for (int h = 0; h < 2; h++) {
        const int t = base + wid * 16 + l4 + h * 8;
        const float inv = 1.f / lrow[h];
        #pragma unroll
        for (int j = 0; j < 8; j++) {
            const float y0 = O[j][2 * h] * inv;
            const float y1 = O[j][2 * h + 1] * inv;
            float l0, l1;
            uint32_t hi = pack_hi(y0, y1, l0, l1);
            uint32_t lo = pack_bf(l0, l1);
            const size_t off = ((size_t)(b * TT + t)) * CC + hh * 64 + j * 8 + qn * 2;
            *(uint32_t*)(g_yhi + off) = hi;
            *(uint32_t*)(g_ylo + off) = lo;
        }
    }
}

// ---------------------------------------------------------------------------
// Fused prep: x -> fp16 split; Wqkv -> single fp16 (transposed);
// Wproj -> bf16 split; K cache -> single fp16; V cache -> fp16 hi/lo (T).
// ---------------------------------------------------------------------------
#define NB_XS 4096
#define NB_WQ 3072
#define NB_WP 1024
#define NB_KC 16384
#define NB_VC 16384
#define NB_TOTAL (NB_XS + NB_WQ + NB_WP + NB_KC + NB_VC)

__global__ __launch_bounds__(256) void prep_fused(
    const float* __restrict__ x,
    const float* __restrict__ kc,
    const float* __restrict__ vc,
    const float* __restrict__ Wqkv,
    const float* __restrict__ Wproj)
{
    __shared__ float tile[32][33];
    const int bid = blockIdx.x;
    const int tid = threadIdx.x;

    if (bid < NB_XS) {
        // ---- x split -> fp16 hi/lo ----
        const int i = bid * 256 + tid;
        float4 v = ((const float4*)x)[i];
        __half hh[4], ll[4];
        float a[4] = {v.x, v.y, v.z, v.w};
        #pragma unroll
        for (int j = 0; j < 4; j++) {
            hh[j] = __float2half_rn(a[j]);
            ll[j] = __float2half_rn(a[j] - __half2float(hh[j]));
        }
        ((uint2*)g_xh16)[i] = *(uint2*)hh;
        ((uint2*)g_xl16)[i] = *(uint2*)ll;
    } else if (bid < NB_XS + NB_WQ) {
        // ---- Wqkv transpose -> single fp16 ----
        const int f = bid - NB_XS;
        const int ntx = 3072 / 32;
        const int nx = (f % ntx) * 32, kx = (f / ntx) * 32;
        const int tx = tid & 31, ty = tid >> 5;
        #pragma unroll
        for (int r = ty; r < 32; r += 8)
            tile[r][tx] = Wqkv[(size_t)(kx + r) * 3072 + nx + tx];
        __syncthreads();
        #pragma unroll
        for (int r = ty; r < 32; r += 8) {
            float xx = tile[tx][r];               // = W[kx+tx][nx+r]
            g_wqh[(size_t)(nx + r) * 1024 + kx + tx] = __float2half_rn(xx);
        }
    } else if (bid < NB_XS + NB_WQ + NB_WP) {
        // ---- Wproj transpose -> bf16 split ----
        const int f = bid - NB_XS - NB_WQ;
        const int ntx = 1024 / 32;
        const int nx = (f % ntx) * 32, kx = (f / ntx) * 32;
        const int tx = tid & 31, ty = tid >> 5;
        #pragma unroll
        for (int r = ty; r < 32; r += 8)
            tile[r][tx] = Wproj[(size_t)(kx + r) * 1024 + nx + tx];
        __syncthreads();
        #pragma unroll
        for (int r = ty; r < 32; r += 8) {
            float xx = tile[tx][r];
            __nv_bfloat16 h = __float2bfloat16_rn(xx);
            __nv_bfloat16 l = __float2bfloat16_rn(xx - __bfloat162float(h));
            size_t o = (size_t)(nx + r) * 1024 + kx + tx;
            g_wp_hi[o] = h;
            g_wp_lo[o] = l;
        }
    } else if (bid < NB_XS + NB_WQ + NB_WP + NB_KC) {
        // ---- K cache -> single fp16 ----
        const size_t i = (size_t)(bid - NB_XS - NB_WQ - NB_WP) * 256 + tid;
        float4 v = ((const float4*)kc)[i];
        const size_t flat = i * 4;
        const size_t bh = flat >> 17;
        const size_t rem = flat & 131071;
        const size_t s = rem >> 6, e = rem & 63;
        __half hv[4];
        float a[4] = {v.x, v.y, v.z, v.w};
        #pragma unroll
        for (int j = 0; j < 4; j++) hv[j] = __float2half_rn(a[j]);
        const size_t off = (bh * SQ + s) * 64 + e;
        *(uint2*)(g_kf + off) = *(uint2*)hv;
    } else {
        // ---- V cache -> transposed fp16 hi/lo ----
        const int f = bid - NB_XS - NB_WQ - NB_WP - NB_KC;
        const int sx = f & 63;
        const int ey = (f >> 6) & 1;
        const int bh = f >> 7;
        const int s0 = sx * 32, e0 = ey * 32;
        const int tx = tid & 31, ty = tid >> 5;
        #pragma unroll
        for (int r = ty; r < 32; r += 8)
            tile[r][tx] = vc[((size_t)bh * LL + s0 + r) * 64 + e0 + tx];
        __syncthreads();
        #pragma unroll
        for (int r = ty; r < 32; r += 8) {
            float xx = tile[tx][r];
            __half h = __float2half_rn(xx);
            __half l = __float2half_rn(xx - __half2float(h));
            const size_t off = ((size_t)bh * 64 + e0 + r) * SQ + s0 + tx;
            g_vthi[off] = h;
            g_vtlo[off] = l;
        }
    }
}

// ---------------------------------------------------------------------------
extern "C" void kernel_launch(void* const* d_in, const int* in_sizes, int n_in,
                              void* d_out, int out_size) {
    const float* x       = (const float*)d_in[0];
    const float* k_cache = (const float*)d_in[1];
    const float* v_cache = (const float*)d_in[2];
    const float* Wqkv    = (const float*)d_in[3];
    const float* bqkv    = (const float*)d_in[4];
    const float* Wproj   = (const float*)d_in[5];
    const float* bproj   = (const float*)d_in[6];
    float* out           = (float*)d_out;

    cudaFuncSetAttribute(qkv_mma_kernel, cudaFuncAttributeMaxDynamicSharedMemorySize,
                         QKV_DYN_BYTES);
    cudaFuncSetAttribute(proj_mma_kernel, cudaFuncAttributeMaxDynamicSharedMemorySize,
                         GEMM_DYN_BYTES);
    cudaFuncSetAttribute(attn_mma_kernel, cudaFuncAttributeMaxDynamicSharedMemorySize,
                         ATT_DYN_BYTES);

    prep_fused<<<NB_TOTAL, 256>>>(x, k_cache, v_cache, Wqkv, Wproj);

    qkv_mma_kernel<<<dim3(24, 32), 256, QKV_DYN_BYTES>>>(bqkv);
    attn_mma_kernel<<<dim3(8, 128), 128, ATT_DYN_BYTES>>>();
    proj_mma_kernel<<<dim3(8, 32), 256, GEMM_DYN_BYTES>>>(bproj, out);
}